// round 8
// baseline (speedup 1.0000x reference)
#include <cuda_runtime.h>
#include <cstdint>
#include <math.h>

// ---------------- problem constants ------------------------------------------
#define T_TOK 4096
#define D_DIM 1024
#define H_DIM 2816
#define E_NUM 8
#define CAP   4096

#define BM 128
#define BN1 64                     // ffn1 N-tile (dual GEMM -> occ 2)
#define BN2 128                    // ffn2 N-tile
#define BK 16
#define RS 20                      // padded smem row stride (floats): conflict-free
#define ATILE_F (BM * RS)          // 2560 floats
#define BTILE1_F (BN1 * RS)        // 1280 floats
#define NK1 (D_DIM / BK)           // 64
#define NK2 (H_DIM / BK)           // 176
#define NSTG 5                     // pipeline ring depth (prefetch distance 3)

#define STG1_F (ATILE_F + 2 * BTILE1_F)        // 5120 floats = 20480 B
#define STG2_F (2 * ATILE_F)                   // 5120 floats = 20480 B
#define SMEM1_BYTES (NSTG * STG1_F * 4)        // 102400
#define SMEM2_BYTES (NSTG * STG2_F * 4)        // 102400

#define N4X ((long)T_TOK * D_DIM / 4)          // 1048576
#define N4W ((long)E_NUM * H_DIM * D_DIM / 4)  // 5767168

// ---------------- static device scratch --------------------------------------
__device__ float g_xc [(size_t)T_TOK * D_DIM];
__device__ float g_W1c[(size_t)E_NUM * H_DIM * D_DIM];
__device__ float g_W2c[(size_t)E_NUM * H_DIM * D_DIM];
__device__ float g_W3c[(size_t)E_NUM * D_DIM * H_DIM];
__device__ float g_Hh [(size_t)E_NUM * CAP * H_DIM];
__device__ float g_Y  [(size_t)E_NUM * CAP * D_DIM];
__device__ int   g_tok[E_NUM * CAP];
__device__ float g_wgt[E_NUM * CAP];
__device__ int   g_cnt[E_NUM];
__device__ int   g_slot[T_TOK * 2];

// ---------------- helpers -----------------------------------------------------
__device__ __forceinline__ uint32_t s2u(const void* p) {
    uint32_t a;
    asm("{ .reg .u64 t; cvta.to.shared.u64 t, %1; cvt.u32.u64 %0, t; }" : "=r"(a) : "l"(p));
    return a;
}

#define CPA16(s, g) asm volatile("cp.async.cg.shared.global [%0], [%1], 16;" :: "r"(s), "l"(g))
#define CPA_COMMIT() asm volatile("cp.async.commit_group;" ::: "memory")
#define CPA_WAIT(n)  asm volatile("cp.async.wait_group %0;" :: "n"(n) : "memory")

// ldmatrix x4: four 8x8-b32 quadrants (as 8x16 b16 tiles)
#define LDSM_X4(r, addr)                                                          \
    asm volatile("ldmatrix.sync.aligned.m8n8.x4.shared.b16 {%0,%1,%2,%3}, [%4];"  \
        : "=r"((r)[0]), "=r"((r)[1]), "=r"((r)[2]), "=r"((r)[3]) : "r"(addr))

// m16n8k8 tf32 MMA, fp32 accum
#define MMA_TF32(d, a, b)                                                         \
    asm volatile(                                                                 \
        "mma.sync.aligned.m16n8k8.row.col.f32.tf32.tf32.f32 "                     \
        "{%0,%1,%2,%3},{%4,%5,%6,%7},{%8,%9},{%0,%1,%2,%3};"                      \
        : "+f"((d)[0]), "+f"((d)[1]), "+f"((d)[2]), "+f"((d)[3])                  \
        : "r"((a)[0]), "r"((a)[1]), "r"((a)[2]), "r"((a)[3]),                     \
          "r"((b)[0]), "r"((b)[1]))

// RN-even round fp32 -> tf32 bit pattern
__device__ __forceinline__ uint32_t tf32r(uint32_t u) {
    uint32_t l = (u >> 13) & 1u;
    return (u + 0xFFFu + l) & 0xFFFFE000u;
}

// ---------------- fused pre-rounding pass (x, W1, W2, W3) --------------------
__global__ void k_round_all(const float4* __restrict__ x,
                            const float4* __restrict__ W1,
                            const float4* __restrict__ W2,
                            const float4* __restrict__ W3,
                            float4* __restrict__ xc,
                            float4* __restrict__ w1c,
                            float4* __restrict__ w2c,
                            float4* __restrict__ w3c) {
    long i = (long)blockIdx.x * 256 + threadIdx.x;
    const float4* s;
    float4* d;
    long off;
    if (i < N4X) { s = x; d = xc; off = i; }
    else {
        long w = i - N4X;
        if (w < N4W)               { s = W1; d = w1c; off = w; }
        else if (w < 2 * N4W)      { s = W2; d = w2c; off = w - N4W; }
        else                       { s = W3; d = w3c; off = w - 2 * N4W; }
    }
    float4 v = s[off];
    float4 o;
    o.x = __uint_as_float(tf32r(__float_as_uint(v.x)));
    o.y = __uint_as_float(tf32r(__float_as_uint(v.y)));
    o.z = __uint_as_float(tf32r(__float_as_uint(v.z)));
    o.w = __uint_as_float(tf32r(__float_as_uint(v.w)));
    d[off] = o;
}

// ---------------- counters / gating / combine --------------------------------
__global__ void k_zero() {
    if (threadIdx.x < E_NUM) g_cnt[threadIdx.x] = 0;
}

__global__ void k_gate(const float* __restrict__ x, const float* __restrict__ Wg) {
    int t = blockIdx.x * (blockDim.x >> 5) + (threadIdx.x >> 5);
    int lane = threadIdx.x & 31;
    if (t >= T_TOK) return;
    const float4* xr = (const float4*)(x + (size_t)t * D_DIM);
    float acc[E_NUM];
#pragma unroll
    for (int e = 0; e < E_NUM; e++) acc[e] = 0.f;
    for (int i = lane; i < D_DIM / 4; i += 32) {
        float4 xv = xr[i];
#pragma unroll
        for (int e = 0; e < E_NUM; e++) {
            float4 wv = ((const float4*)(Wg + (size_t)e * D_DIM))[i];
            acc[e] += xv.x * wv.x + xv.y * wv.y + xv.z * wv.z + xv.w * wv.w;
        }
    }
#pragma unroll
    for (int e = 0; e < E_NUM; e++)
#pragma unroll
        for (int o = 16; o > 0; o >>= 1)
            acc[e] += __shfl_xor_sync(0xffffffffu, acc[e], o);
    if (lane == 0) {
        int e0 = 0; float v0 = acc[0];
#pragma unroll
        for (int e = 1; e < E_NUM; e++) if (acc[e] > v0) { v0 = acc[e]; e0 = e; }
        int e1 = -1; float v1 = -INFINITY;
#pragma unroll
        for (int e = 0; e < E_NUM; e++)
            if (e != e0 && acc[e] > v1) { v1 = acc[e]; e1 = e; }
        int i0 = atomicAdd(&g_cnt[e0], 1);
        g_tok[e0 * CAP + i0] = t; g_wgt[e0 * CAP + i0] = v0;
        g_slot[t * 2 + 0] = e0 * CAP + i0;
        int i1 = atomicAdd(&g_cnt[e1], 1);
        g_tok[e1 * CAP + i1] = t; g_wgt[e1 * CAP + i1] = v1;
        g_slot[t * 2 + 1] = e1 * CAP + i1;
    }
}

__global__ void k_combine(float* __restrict__ out) {
    int idx = blockIdx.x * 256 + threadIdx.x;
    int t = idx >> 8;
    int c = idx & 255;
    int s0 = g_slot[t * 2 + 0];
    int s1 = g_slot[t * 2 + 1];
    const float4* Y4 = (const float4*)g_Y;
    float4 a = Y4[(size_t)s0 * (D_DIM / 4) + c];
    float4 b = Y4[(size_t)s1 * (D_DIM / 4) + c];
    float4 o; o.x = a.x + b.x; o.y = a.y + b.y; o.z = a.z + b.z; o.w = a.w + b.w;
    ((float4*)out)[idx] = o;
}

// ---------------- GEMM1: Hh = silu(X W1^T) * (X W2^T) ------------------------
// 128x64 dual tile, warp tile 64x16, occ 2. 5-stage ring, barrier per 2 k-iters.
__global__ __launch_bounds__(256, 2)
void k_ffn1() {
    int e  = blockIdx.x >> 5;
    int m0 = (blockIdx.x & 31) * BM;
    int cnt = g_cnt[e];
    if (m0 >= cnt) return;
    int n0 = blockIdx.y * BN1;

    extern __shared__ float sm[];

    int tid  = threadIdx.x;
    int wid  = tid >> 5, lane = tid & 31;
    int wm0  = (wid & 1) * 64;
    int wn0  = (wid >> 1) * 16;
    int grp  = lane >> 2, tg = lane & 3;

    // ldmatrix lane geometry
    int lt = lane >> 3, lr = lane & 7;
    uint32_t smb = s2u(sm);
    uint32_t aAdr = smb + (uint32_t)((wm0 + (lt & 1) * 8 + lr) * RS + (lt >> 1) * 4) * 4u;
    uint32_t bAdr = smb + (uint32_t)((wn0 + (lt >> 1) * 8 + lr) * RS + (lt & 1) * 4) * 4u;

    // A loader: row = tid/2 (0..127), col base = (tid&1)*8 -> 2x CPA16
    int lrow = tid >> 1;
    int lc   = (tid & 1) * 8;
    int tok  = g_tok[e * CAP + m0 + lrow];
    tok = min(max(tok, 0), T_TOK - 1);
    const float* aS  = g_xc + (size_t)tok * D_DIM + lc;
    uint32_t dstA = smb + (uint32_t)(lrow * RS + lc) * 4u;
    // B loader: row = tid/4 (0..63), col = (tid&3)*4 -> 1x CPA16 per matrix
    int brow = tid >> 2;
    int bc   = (tid & 3) * 4;
    const float* b1S = g_W1c + ((size_t)e * H_DIM + n0 + brow) * D_DIM + bc;
    const float* b2S = g_W2c + ((size_t)e * H_DIM + n0 + brow) * D_DIM + bc;
    uint32_t dstB = smb + (uint32_t)(ATILE_F + brow * RS + bc) * 4u;

#define LOAD1(k, stg) do {                                                      \
        int kc = (k) * BK;                                                      \
        uint32_t o = (uint32_t)(stg) * STG1_F * 4u;                             \
        CPA16(dstA + o,      aS + kc);                                          \
        CPA16(dstA + o + 16, aS + kc + 4);                                      \
        CPA16(dstB + o,                  b1S + kc);                             \
        CPA16(dstB + o + BTILE1_F * 4u,  b2S + kc);                             \
    } while (0)

    float accG[4][2][4], accU[4][2][4];
#pragma unroll
    for (int i = 0; i < 4; i++)
#pragma unroll
        for (int j = 0; j < 2; j++)
#pragma unroll
            for (int r = 0; r < 4; r++) { accG[i][j][r] = 0.f; accU[i][j][r] = 0.f; }

#define COMPUTE1(cs) do {                                                       \
        uint32_t sA  = aAdr + (uint32_t)((cs) * STG1_F) * 4u;                   \
        uint32_t sB1 = bAdr + (uint32_t)((cs) * STG1_F + ATILE_F) * 4u;         \
        uint32_t sB2 = sB1 + (uint32_t)(BTILE1_F) * 4u;                         \
        _Pragma("unroll")                                                       \
        for (int ks = 0; ks < 2; ks++) {                                        \
            uint32_t a[4][4];                                                   \
            _Pragma("unroll")                                                   \
            for (int mt = 0; mt < 4; mt++)                                      \
                LDSM_X4(a[mt], sA + (uint32_t)(mt * 16 * RS + ks * 8) * 4u);    \
            uint32_t b1[4], b2[4];                                              \
            LDSM_X4(b1, sB1 + (uint32_t)(ks * 8) * 4u);                         \
            LDSM_X4(b2, sB2 + (uint32_t)(ks * 8) * 4u);                         \
            _Pragma("unroll")                                                   \
            for (int mt = 0; mt < 4; mt++)                                      \
                _Pragma("unroll")                                               \
                for (int nt = 0; nt < 2; nt++) {                                \
                    MMA_TF32(accG[mt][nt], a[mt], &b1[nt * 2]);                 \
                    MMA_TF32(accU[mt][nt], a[mt], &b2[nt * 2]);                 \
                }                                                               \
        }                                                                       \
    } while (0)

    LOAD1(0, 0); CPA_COMMIT();
    LOAD1(1, 1); CPA_COMMIT();
    LOAD1(2, 2); CPA_COMMIT();

    int cs = 0, ls = 3;
    for (int k = 0; k < NK1; k += 2) {
        CPA_WAIT(1);                 // groups <= k+2 done: stages <= k+1 complete
        __syncthreads();             // publish stages k, k+1; retire reads <= k-1
        if (k + 3 < NK1) LOAD1(k + 3, ls);
        CPA_COMMIT();
        if (++ls == NSTG) ls = 0;
        COMPUTE1(cs);                // stage k
        if (++cs == NSTG) cs = 0;
        if (k + 4 < NK1) LOAD1(k + 4, ls);
        CPA_COMMIT();
        if (++ls == NSTG) ls = 0;
        COMPUTE1(cs);                // stage k+1
        if (++cs == NSTG) cs = 0;
    }
#undef LOAD1
#undef COMPUTE1

    // epilogue: h = tf32(silu(g) * u)
#pragma unroll
    for (int mt = 0; mt < 4; mt++) {
#pragma unroll
        for (int nt = 0; nt < 2; nt++) {
            int r0 = m0 + wm0 + mt * 16 + grp;
            int cc = n0 + wn0 + nt * 8 + 2 * tg;
#pragma unroll
            for (int h = 0; h < 2; h++) {
                int row = r0 + h * 8;
                if (row < cnt) {
                    float gv0 = accG[mt][nt][2 * h + 0], uv0 = accU[mt][nt][2 * h + 0];
                    float gv1 = accG[mt][nt][2 * h + 1], uv1 = accU[mt][nt][2 * h + 1];
                    float h0 = (gv0 / (1.f + __expf(-gv0))) * uv0;
                    float h1 = (gv1 / (1.f + __expf(-gv1))) * uv1;
                    float2 o;
                    o.x = __uint_as_float(tf32r(__float_as_uint(h0)));
                    o.y = __uint_as_float(tf32r(__float_as_uint(h1)));
                    *(float2*)&g_Hh[((size_t)e * CAP + row) * H_DIM + cc] = o;
                }
            }
        }
    }
}

// ---------------- GEMM2: Y = wgt * (Hh @ W3[e]^T) ----------------------------
__global__ __launch_bounds__(256, 2)
void k_ffn2() {
    int e  = blockIdx.x >> 5;
    int m0 = (blockIdx.x & 31) * BM;
    int cnt = g_cnt[e];
    if (m0 >= cnt) return;
    int n0 = blockIdx.y * BN2;

    extern __shared__ float sm[];

    int tid  = threadIdx.x;
    int wid  = tid >> 5, lane = tid & 31;
    int wm0  = (wid & 1) * 64;
    int wn0  = (wid >> 1) * 32;
    int grp  = lane >> 2, tg = lane & 3;

    int lt = lane >> 3, lr = lane & 7;
    uint32_t smb = s2u(sm);
    uint32_t aAdr = smb + (uint32_t)((wm0 + (lt & 1) * 8 + lr) * RS + (lt >> 1) * 4) * 4u;
    uint32_t bAdr = smb + (uint32_t)((wn0 + (lt >> 1) * 8 + lr) * RS + (lt & 1) * 4) * 4u;

    int lrow = tid >> 1;
    int lc   = (tid & 1) * 8;
    const float* aS = g_Hh  + ((size_t)e * CAP + m0 + lrow) * H_DIM + lc;
    const float* bS = g_W3c + ((size_t)e * D_DIM + n0 + lrow) * H_DIM + lc;
    uint32_t dst = smb + (uint32_t)(lrow * RS + lc) * 4u;

#define LOAD2(k, stg) do {                                                      \
        int kc = (k) * BK;                                                      \
        uint32_t d0 = dst + (uint32_t)(stg) * STG2_F * 4u;                      \
        CPA16(d0,               aS + kc); CPA16(d0 + 16,               aS + kc + 4); \
        CPA16(d0 + ATILE_F * 4, bS + kc); CPA16(d0 + ATILE_F * 4 + 16, bS + kc + 4); \
    } while (0)

    float acc[4][4][4];
#pragma unroll
    for (int i = 0; i < 4; i++)
#pragma unroll
        for (int j = 0; j < 4; j++)
#pragma unroll
            for (int r = 0; r < 4; r++) acc[i][j][r] = 0.f;

#define COMPUTE2(cs) do {                                                       \
        uint32_t sA = aAdr + (uint32_t)((cs) * STG2_F) * 4u;                    \
        uint32_t sB = bAdr + (uint32_t)((cs) * STG2_F + ATILE_F) * 4u;          \
        _Pragma("unroll")                                                       \
        for (int ks = 0; ks < 2; ks++) {                                        \
            uint32_t a[4][4];                                                   \
            _Pragma("unroll")                                                   \
            for (int mt = 0; mt < 4; mt++)                                      \
                LDSM_X4(a[mt], sA + (uint32_t)(mt * 16 * RS + ks * 8) * 4u);    \
            uint32_t b[2][4];                                                   \
            _Pragma("unroll")                                                   \
            for (int p = 0; p < 2; p++)                                         \
                LDSM_X4(b[p], sB + (uint32_t)(p * 16 * RS + ks * 8) * 4u);      \
            _Pragma("unroll")                                                   \
            for (int mt = 0; mt < 4; mt++)                                      \
                _Pragma("unroll")                                               \
                for (int nt = 0; nt < 4; nt++)                                  \
                    MMA_TF32(acc[mt][nt], a[mt], &b[nt >> 1][(nt & 1) * 2]);    \
        }                                                                       \
    } while (0)

    LOAD2(0, 0); CPA_COMMIT();
    LOAD2(1, 1); CPA_COMMIT();
    LOAD2(2, 2); CPA_COMMIT();

    int cs = 0, ls = 3;
    for (int k = 0; k < NK2; k += 2) {
        CPA_WAIT(1);
        __syncthreads();
        if (k + 3 < NK2) LOAD2(k + 3, ls);
        CPA_COMMIT();
        if (++ls == NSTG) ls = 0;
        COMPUTE2(cs);
        if (++cs == NSTG) cs = 0;
        if (k + 4 < NK2) LOAD2(k + 4, ls);
        CPA_COMMIT();
        if (++ls == NSTG) ls = 0;
        COMPUTE2(cs);
        if (++cs == NSTG) cs = 0;
    }
#undef LOAD2
#undef COMPUTE2

#pragma unroll
    for (int mt = 0; mt < 4; mt++) {
        int r0 = m0 + wm0 + mt * 16 + grp;
#pragma unroll
        for (int h = 0; h < 2; h++) {
            int row = r0 + h * 8;
            if (row < cnt) {
                float w = g_wgt[e * CAP + row];
#pragma unroll
                for (int nt = 0; nt < 4; nt++) {
                    int cc = n0 + wn0 + nt * 8 + 2 * tg;
                    float2 o;
                    o.x = acc[mt][nt][2 * h + 0] * w;
                    o.y = acc[mt][nt][2 * h + 1] * w;
                    *(float2*)&g_Y[((size_t)e * CAP + row) * D_DIM + cc] = o;
                }
            }
        }
    }
}

// -----------------------------------------------------------------------------
extern "C" void kernel_launch(void* const* d_in, const int* in_sizes, int n_in,
                              void* d_out, int out_size) {
    const float* x  = (const float*)d_in[0];
    const float* Wg = (const float*)d_in[1];
    const float* W1 = (const float*)d_in[2];
    const float* W2 = (const float*)d_in[3];
    const float* W3 = (const float*)d_in[4];
    float* out = (float*)d_out;

    cudaFuncSetAttribute(k_ffn1, cudaFuncAttributeMaxDynamicSharedMemorySize, SMEM1_BYTES);
    cudaFuncSetAttribute(k_ffn2, cudaFuncAttributeMaxDynamicSharedMemorySize, SMEM2_BYTES);

    void *p_xc, *p_w1, *p_w2, *p_w3;
    cudaGetSymbolAddress(&p_xc, g_xc);
    cudaGetSymbolAddress(&p_w1, g_W1c);
    cudaGetSymbolAddress(&p_w2, g_W2c);
    cudaGetSymbolAddress(&p_w3, g_W3c);

    long n4_total = N4X + 3 * N4W;                     // 18350080
    int  nblk     = (int)((n4_total + 255) / 256);     // 71680

    k_round_all<<<nblk, 256>>>((const float4*)x,  (const float4*)W1,
                               (const float4*)W2, (const float4*)W3,
                               (float4*)p_xc, (float4*)p_w1,
                               (float4*)p_w2, (float4*)p_w3);          // 1
    k_zero<<<1, 32>>>();                                               // 2
    k_gate<<<T_TOK / 8, 256>>>(x, Wg);                                 // 3

    dim3 g1(E_NUM * (CAP / BM), H_DIM / BN1);  // (256, 44)
    k_ffn1<<<g1, 256, SMEM1_BYTES>>>();                                // 4 <- profile target
    dim3 g2(E_NUM * (CAP / BM), D_DIM / BN2);  // (256, 8)
    k_ffn2<<<g2, 256, SMEM2_BYTES>>>();                                // 5 <- profile target

    k_combine<<<(T_TOK * D_DIM / 4) / 256, 256>>>(out);                // 6
}

// round 9
// speedup vs baseline: 1.0361x; 1.0361x over previous
#include <cuda_runtime.h>
#include <cstdint>
#include <math.h>

// ---------------- problem constants ------------------------------------------
#define T_TOK 4096
#define D_DIM 1024
#define H_DIM 2816
#define E_NUM 8
#define CAP   4096

#define BM 128
#define BN 128
#define BK 16
#define RS 20                      // padded smem row stride (floats): conflict-free
#define ATILE_F (BM * RS)          // 2560 floats
#define NK1 (D_DIM / BK)           // 64
#define NK2 (H_DIM / BK)           // 176
#define NSTG 5                     // pipeline ring depth (prefetch distance 3)

#define STG1_F (3 * ATILE_F)                   // A + B1 + B2
#define STG2_F (2 * ATILE_F)                   // A + B
#define SMEM1_BYTES (NSTG * STG1_F * 4)        // 153600
#define SMEM2_BYTES (NSTG * STG2_F * 4)        // 102400

#define N4X ((long)T_TOK * D_DIM / 4)          // 1048576
#define N4W ((long)E_NUM * H_DIM * D_DIM / 4)  // 5767168

// ---------------- static device scratch --------------------------------------
__device__ float g_xc [(size_t)T_TOK * D_DIM];
__device__ float g_W1c[(size_t)E_NUM * H_DIM * D_DIM];
__device__ float g_W2c[(size_t)E_NUM * H_DIM * D_DIM];
__device__ float g_W3c[(size_t)E_NUM * D_DIM * H_DIM];
__device__ float g_Hh [(size_t)E_NUM * CAP * H_DIM];
__device__ float g_Y  [(size_t)E_NUM * CAP * D_DIM];
__device__ int   g_tok[E_NUM * CAP];
__device__ float g_wgt[E_NUM * CAP];
__device__ int   g_cnt[E_NUM];
__device__ int   g_slot[T_TOK * 2];

// ---------------- helpers -----------------------------------------------------
__device__ __forceinline__ uint32_t s2u(const void* p) {
    uint32_t a;
    asm("{ .reg .u64 t; cvta.to.shared.u64 t, %1; cvt.u32.u64 %0, t; }" : "=r"(a) : "l"(p));
    return a;
}

#define CPA16(s, g) asm volatile("cp.async.cg.shared.global [%0], [%1], 16;" :: "r"(s), "l"(g))
#define CPA_COMMIT() asm volatile("cp.async.commit_group;" ::: "memory")
#define CPA_WAIT(n)  asm volatile("cp.async.wait_group %0;" :: "n"(n) : "memory")

// ldmatrix x4: four 8x8-b32 quadrants (as 8x16 b16 tiles)
#define LDSM_X4(r, addr)                                                          \
    asm volatile("ldmatrix.sync.aligned.m8n8.x4.shared.b16 {%0,%1,%2,%3}, [%4];"  \
        : "=r"((r)[0]), "=r"((r)[1]), "=r"((r)[2]), "=r"((r)[3]) : "r"(addr))

// m16n8k8 tf32 MMA, fp32 accum
#define MMA_TF32(d, a, b)                                                         \
    asm volatile(                                                                 \
        "mma.sync.aligned.m16n8k8.row.col.f32.tf32.tf32.f32 "                     \
        "{%0,%1,%2,%3},{%4,%5,%6,%7},{%8,%9},{%0,%1,%2,%3};"                      \
        : "+f"((d)[0]), "+f"((d)[1]), "+f"((d)[2]), "+f"((d)[3])                  \
        : "r"((a)[0]), "r"((a)[1]), "r"((a)[2]), "r"((a)[3]),                     \
          "r"((b)[0]), "r"((b)[1]))

// RN-even round fp32 -> tf32 bit pattern
__device__ __forceinline__ uint32_t tf32r(uint32_t u) {
    uint32_t l = (u >> 13) & 1u;
    return (u + 0xFFFu + l) & 0xFFFFE000u;
}

// ---------------- fused pre-rounding pass (x, W1, W2, W3) --------------------
__global__ void k_round_all(const float4* __restrict__ x,
                            const float4* __restrict__ W1,
                            const float4* __restrict__ W2,
                            const float4* __restrict__ W3,
                            float4* __restrict__ xc,
                            float4* __restrict__ w1c,
                            float4* __restrict__ w2c,
                            float4* __restrict__ w3c) {
    long i = (long)blockIdx.x * 256 + threadIdx.x;
    const float4* s;
    float4* d;
    long off;
    if (i < N4X) { s = x; d = xc; off = i; }
    else {
        long w = i - N4X;
        if (w < N4W)               { s = W1; d = w1c; off = w; }
        else if (w < 2 * N4W)      { s = W2; d = w2c; off = w - N4W; }
        else                       { s = W3; d = w3c; off = w - 2 * N4W; }
    }
    float4 v = s[off];
    float4 o;
    o.x = __uint_as_float(tf32r(__float_as_uint(v.x)));
    o.y = __uint_as_float(tf32r(__float_as_uint(v.y)));
    o.z = __uint_as_float(tf32r(__float_as_uint(v.z)));
    o.w = __uint_as_float(tf32r(__float_as_uint(v.w)));
    d[off] = o;
}

// ---------------- counters / gating / combine --------------------------------
__global__ void k_zero() {
    if (threadIdx.x < E_NUM) g_cnt[threadIdx.x] = 0;
}

__global__ void k_gate(const float* __restrict__ x, const float* __restrict__ Wg) {
    int t = blockIdx.x * (blockDim.x >> 5) + (threadIdx.x >> 5);
    int lane = threadIdx.x & 31;
    if (t >= T_TOK) return;
    const float4* xr = (const float4*)(x + (size_t)t * D_DIM);
    float acc[E_NUM];
#pragma unroll
    for (int e = 0; e < E_NUM; e++) acc[e] = 0.f;
    for (int i = lane; i < D_DIM / 4; i += 32) {
        float4 xv = xr[i];
#pragma unroll
        for (int e = 0; e < E_NUM; e++) {
            float4 wv = ((const float4*)(Wg + (size_t)e * D_DIM))[i];
            acc[e] += xv.x * wv.x + xv.y * wv.y + xv.z * wv.z + xv.w * wv.w;
        }
    }
#pragma unroll
    for (int e = 0; e < E_NUM; e++)
#pragma unroll
        for (int o = 16; o > 0; o >>= 1)
            acc[e] += __shfl_xor_sync(0xffffffffu, acc[e], o);
    if (lane == 0) {
        int e0 = 0; float v0 = acc[0];
#pragma unroll
        for (int e = 1; e < E_NUM; e++) if (acc[e] > v0) { v0 = acc[e]; e0 = e; }
        int e1 = -1; float v1 = -INFINITY;
#pragma unroll
        for (int e = 0; e < E_NUM; e++)
            if (e != e0 && acc[e] > v1) { v1 = acc[e]; e1 = e; }
        int i0 = atomicAdd(&g_cnt[e0], 1);
        g_tok[e0 * CAP + i0] = t; g_wgt[e0 * CAP + i0] = v0;
        g_slot[t * 2 + 0] = e0 * CAP + i0;
        int i1 = atomicAdd(&g_cnt[e1], 1);
        g_tok[e1 * CAP + i1] = t; g_wgt[e1 * CAP + i1] = v1;
        g_slot[t * 2 + 1] = e1 * CAP + i1;
    }
}

__global__ void k_combine(float* __restrict__ out) {
    int idx = blockIdx.x * 256 + threadIdx.x;
    int t = idx >> 8;
    int c = idx & 255;
    int s0 = g_slot[t * 2 + 0];
    int s1 = g_slot[t * 2 + 1];
    const float4* Y4 = (const float4*)g_Y;
    float4 a = Y4[(size_t)s0 * (D_DIM / 4) + c];
    float4 b = Y4[(size_t)s1 * (D_DIM / 4) + c];
    float4 o; o.x = a.x + b.x; o.y = a.y + b.y; o.z = a.z + b.z; o.w = a.w + b.w;
    ((float4*)out)[idx] = o;
}

// ---------------- GEMM1: Hh = silu(X W1^T) * (X W2^T) ------------------------
// 128x128 dual tile, 512 threads (16 warps, warp tile 32x32), occ 1.
// 5-stage cp.async ring, prefetch distance 3, one barrier per 2 k-iters.
__global__ __launch_bounds__(512, 1)
void k_ffn1() {
    int e  = blockIdx.x >> 5;
    int m0 = (blockIdx.x & 31) * BM;
    int cnt = g_cnt[e];
    if (m0 >= cnt) return;
    int n0 = blockIdx.y * BN;

    extern __shared__ float sm[];

    int tid  = threadIdx.x;
    int wid  = tid >> 5, lane = tid & 31;
    int wm0  = (wid & 3) * 32;        // 4 m-partitions
    int wn0  = (wid >> 2) * 32;       // 4 n-partitions
    int grp  = lane >> 2, tg = lane & 3;

    // ldmatrix lane geometry
    int lt = lane >> 3, lr = lane & 7;
    uint32_t smb = s2u(sm);
    uint32_t aAdr = smb + (uint32_t)((wm0 + (lt & 1) * 8 + lr) * RS + (lt >> 1) * 4) * 4u;
    uint32_t bAdr = smb + (uint32_t)((wn0 + (lt >> 1) * 8 + lr) * RS + (lt & 1) * 4) * 4u;

    // loader: 512 threads, one CPA16 per tile each. row = tid/4, col = (tid&3)*4
    int lrow = tid >> 2;
    int lc   = (tid & 3) * 4;
    int tok  = g_tok[e * CAP + m0 + lrow];
    tok = min(max(tok, 0), T_TOK - 1);
    const float* aS  = g_xc  + (size_t)tok * D_DIM + lc;
    const float* b1S = g_W1c + ((size_t)e * H_DIM + n0 + lrow) * D_DIM + lc;
    const float* b2S = g_W2c + ((size_t)e * H_DIM + n0 + lrow) * D_DIM + lc;
    uint32_t dst = smb + (uint32_t)(lrow * RS + lc) * 4u;

#define LOAD1(k, stg) do {                                                      \
        int kc = (k) * BK;                                                      \
        uint32_t o = (uint32_t)(stg) * STG1_F * 4u;                             \
        CPA16(dst + o,                     aS  + kc);                           \
        CPA16(dst + o + ATILE_F * 4u,      b1S + kc);                           \
        CPA16(dst + o + 2u * ATILE_F * 4u, b2S + kc);                           \
    } while (0)

    float accG[2][4][4], accU[2][4][4];
#pragma unroll
    for (int i = 0; i < 2; i++)
#pragma unroll
        for (int j = 0; j < 4; j++)
#pragma unroll
            for (int r = 0; r < 4; r++) { accG[i][j][r] = 0.f; accU[i][j][r] = 0.f; }

#define COMPUTE1(cs) do {                                                       \
        uint32_t sA  = aAdr + (uint32_t)((cs) * STG1_F) * 4u;                   \
        uint32_t sB1 = bAdr + (uint32_t)((cs) * STG1_F + ATILE_F) * 4u;         \
        uint32_t sB2 = sB1 + (uint32_t)(ATILE_F) * 4u;                          \
        _Pragma("unroll")                                                       \
        for (int ks = 0; ks < 2; ks++) {                                        \
            uint32_t a[2][4];                                                   \
            _Pragma("unroll")                                                   \
            for (int mt = 0; mt < 2; mt++)                                      \
                LDSM_X4(a[mt], sA + (uint32_t)(mt * 16 * RS + ks * 8) * 4u);    \
            uint32_t b1[2][4], b2[2][4];                                        \
            _Pragma("unroll")                                                   \
            for (int p = 0; p < 2; p++) {                                       \
                LDSM_X4(b1[p], sB1 + (uint32_t)(p * 16 * RS + ks * 8) * 4u);    \
                LDSM_X4(b2[p], sB2 + (uint32_t)(p * 16 * RS + ks * 8) * 4u);    \
            }                                                                   \
            _Pragma("unroll")                                                   \
            for (int mt = 0; mt < 2; mt++)                                      \
                _Pragma("unroll")                                               \
                for (int nt = 0; nt < 4; nt++) {                                \
                    MMA_TF32(accG[mt][nt], a[mt], &b1[nt >> 1][(nt & 1) * 2]);  \
                    MMA_TF32(accU[mt][nt], a[mt], &b2[nt >> 1][(nt & 1) * 2]);  \
                }                                                               \
        }                                                                       \
    } while (0)

    LOAD1(0, 0); CPA_COMMIT();
    LOAD1(1, 1); CPA_COMMIT();
    LOAD1(2, 2); CPA_COMMIT();

    int cs = 0, ls = 3;
    for (int k = 0; k < NK1; k += 2) {
        CPA_WAIT(1);                 // groups <= k+2 done: stages <= k+1 complete
        __syncthreads();             // publish stages k, k+1; retire reads <= k-1
        if (k + 3 < NK1) LOAD1(k + 3, ls);
        CPA_COMMIT();
        if (++ls == NSTG) ls = 0;
        COMPUTE1(cs);                // stage k
        if (++cs == NSTG) cs = 0;
        if (k + 4 < NK1) LOAD1(k + 4, ls);
        CPA_COMMIT();
        if (++ls == NSTG) ls = 0;
        COMPUTE1(cs);                // stage k+1
        if (++cs == NSTG) cs = 0;
    }
#undef LOAD1
#undef COMPUTE1

    // epilogue: h = tf32(silu(g) * u)
#pragma unroll
    for (int mt = 0; mt < 2; mt++) {
#pragma unroll
        for (int nt = 0; nt < 4; nt++) {
            int r0 = m0 + wm0 + mt * 16 + grp;
            int cc = n0 + wn0 + nt * 8 + 2 * tg;
#pragma unroll
            for (int h = 0; h < 2; h++) {
                int row = r0 + h * 8;
                if (row < cnt) {
                    float gv0 = accG[mt][nt][2 * h + 0], uv0 = accU[mt][nt][2 * h + 0];
                    float gv1 = accG[mt][nt][2 * h + 1], uv1 = accU[mt][nt][2 * h + 1];
                    float h0 = (gv0 / (1.f + __expf(-gv0))) * uv0;
                    float h1 = (gv1 / (1.f + __expf(-gv1))) * uv1;
                    float2 o;
                    o.x = __uint_as_float(tf32r(__float_as_uint(h0)));
                    o.y = __uint_as_float(tf32r(__float_as_uint(h1)));
                    *(float2*)&g_Hh[((size_t)e * CAP + row) * H_DIM + cc] = o;
                }
            }
        }
    }
}

// ---------------- GEMM2: Y = wgt * (Hh @ W3[e]^T) ----------------------------
// Unchanged from R7: 256 threads, warp tile 64x32, occ 2.
__global__ __launch_bounds__(256, 2)
void k_ffn2() {
    int e  = blockIdx.x >> 5;
    int m0 = (blockIdx.x & 31) * BM;
    int cnt = g_cnt[e];
    if (m0 >= cnt) return;
    int n0 = blockIdx.y * BN;

    extern __shared__ float sm[];

    int tid  = threadIdx.x;
    int wid  = tid >> 5, lane = tid & 31;
    int wm0  = (wid & 1) * 64;
    int wn0  = (wid >> 1) * 32;
    int grp  = lane >> 2, tg = lane & 3;

    int lt = lane >> 3, lr = lane & 7;
    uint32_t smb = s2u(sm);
    uint32_t aAdr = smb + (uint32_t)((wm0 + (lt & 1) * 8 + lr) * RS + (lt >> 1) * 4) * 4u;
    uint32_t bAdr = smb + (uint32_t)((wn0 + (lt >> 1) * 8 + lr) * RS + (lt & 1) * 4) * 4u;

    int lrow = tid >> 1;
    int lc   = (tid & 1) * 8;
    const float* aS = g_Hh  + ((size_t)e * CAP + m0 + lrow) * H_DIM + lc;
    const float* bS = g_W3c + ((size_t)e * D_DIM + n0 + lrow) * H_DIM + lc;
    uint32_t dst = smb + (uint32_t)(lrow * RS + lc) * 4u;

#define LOAD2(k, stg) do {                                                      \
        int kc = (k) * BK;                                                      \
        uint32_t d0 = dst + (uint32_t)(stg) * STG2_F * 4u;                      \
        CPA16(d0,               aS + kc); CPA16(d0 + 16,               aS + kc + 4); \
        CPA16(d0 + ATILE_F * 4, bS + kc); CPA16(d0 + ATILE_F * 4 + 16, bS + kc + 4); \
    } while (0)

    float acc[4][4][4];
#pragma unroll
    for (int i = 0; i < 4; i++)
#pragma unroll
        for (int j = 0; j < 4; j++)
#pragma unroll
            for (int r = 0; r < 4; r++) acc[i][j][r] = 0.f;

#define COMPUTE2(cs) do {                                                       \
        uint32_t sA = aAdr + (uint32_t)((cs) * STG2_F) * 4u;                    \
        uint32_t sB = bAdr + (uint32_t)((cs) * STG2_F + ATILE_F) * 4u;          \
        _Pragma("unroll")                                                       \
        for (int ks = 0; ks < 2; ks++) {                                        \
            uint32_t a[4][4];                                                   \
            _Pragma("unroll")                                                   \
            for (int mt = 0; mt < 4; mt++)                                      \
                LDSM_X4(a[mt], sA + (uint32_t)(mt * 16 * RS + ks * 8) * 4u);    \
            uint32_t b[2][4];                                                   \
            _Pragma("unroll")                                                   \
            for (int p = 0; p < 2; p++)                                         \
                LDSM_X4(b[p], sB + (uint32_t)(p * 16 * RS + ks * 8) * 4u);      \
            _Pragma("unroll")                                                   \
            for (int mt = 0; mt < 4; mt++)                                      \
                _Pragma("unroll")                                               \
                for (int nt = 0; nt < 4; nt++)                                  \
                    MMA_TF32(acc[mt][nt], a[mt], &b[nt >> 1][(nt & 1) * 2]);    \
        }                                                                       \
    } while (0)

    LOAD2(0, 0); CPA_COMMIT();
    LOAD2(1, 1); CPA_COMMIT();
    LOAD2(2, 2); CPA_COMMIT();

    int cs = 0, ls = 3;
    for (int k = 0; k < NK2; k += 2) {
        CPA_WAIT(1);
        __syncthreads();
        if (k + 3 < NK2) LOAD2(k + 3, ls);
        CPA_COMMIT();
        if (++ls == NSTG) ls = 0;
        COMPUTE2(cs);
        if (++cs == NSTG) cs = 0;
        if (k + 4 < NK2) LOAD2(k + 4, ls);
        CPA_COMMIT();
        if (++ls == NSTG) ls = 0;
        COMPUTE2(cs);
        if (++cs == NSTG) cs = 0;
    }
#undef LOAD2
#undef COMPUTE2

#pragma unroll
    for (int mt = 0; mt < 4; mt++) {
        int r0 = m0 + wm0 + mt * 16 + grp;
#pragma unroll
        for (int h = 0; h < 2; h++) {
            int row = r0 + h * 8;
            if (row < cnt) {
                float w = g_wgt[e * CAP + row];
#pragma unroll
                for (int nt = 0; nt < 4; nt++) {
                    int cc = n0 + wn0 + nt * 8 + 2 * tg;
                    float2 o;
                    o.x = acc[mt][nt][2 * h + 0] * w;
                    o.y = acc[mt][nt][2 * h + 1] * w;
                    *(float2*)&g_Y[((size_t)e * CAP + row) * D_DIM + cc] = o;
                }
            }
        }
    }
}

// -----------------------------------------------------------------------------
extern "C" void kernel_launch(void* const* d_in, const int* in_sizes, int n_in,
                              void* d_out, int out_size) {
    const float* x  = (const float*)d_in[0];
    const float* Wg = (const float*)d_in[1];
    const float* W1 = (const float*)d_in[2];
    const float* W2 = (const float*)d_in[3];
    const float* W3 = (const float*)d_in[4];
    float* out = (float*)d_out;

    cudaFuncSetAttribute(k_ffn1, cudaFuncAttributeMaxDynamicSharedMemorySize, SMEM1_BYTES);
    cudaFuncSetAttribute(k_ffn2, cudaFuncAttributeMaxDynamicSharedMemorySize, SMEM2_BYTES);

    void *p_xc, *p_w1, *p_w2, *p_w3;
    cudaGetSymbolAddress(&p_xc, g_xc);
    cudaGetSymbolAddress(&p_w1, g_W1c);
    cudaGetSymbolAddress(&p_w2, g_W2c);
    cudaGetSymbolAddress(&p_w3, g_W3c);

    long n4_total = N4X + 3 * N4W;                     // 18350080
    int  nblk     = (int)((n4_total + 255) / 256);     // 71680

    k_round_all<<<nblk, 256>>>((const float4*)x,  (const float4*)W1,
                               (const float4*)W2, (const float4*)W3,
                               (float4*)p_xc, (float4*)p_w1,
                               (float4*)p_w2, (float4*)p_w3);          // 1
    k_zero<<<1, 32>>>();                                               // 2
    k_gate<<<T_TOK / 8, 256>>>(x, Wg);                                 // 3

    dim3 g1(E_NUM * (CAP / BM), H_DIM / BN);   // (256, 22)
    k_ffn1<<<g1, 512, SMEM1_BYTES>>>();                                // 4 <- profile target
    dim3 g2(E_NUM * (CAP / BM), D_DIM / BN);   // (256, 8)
    k_ffn2<<<g2, 256, SMEM2_BYTES>>>();                                // 5 <- profile target

    k_combine<<<(T_TOK * D_DIM / 4) / 256, 256>>>(out);                // 6
}

// round 10
// speedup vs baseline: 1.3699x; 1.3222x over previous
#include <cuda_runtime.h>
#include <cstdint>
#include <math.h>

// ---------------- problem constants ------------------------------------------
#define T_TOK 4096
#define D_DIM 1024
#define H_DIM 2816
#define E_NUM 8
#define CAP   4096

#define BM 128
#define BN 128
#define BK 16
#define RS 20                      // padded smem row stride (floats): conflict-free
#define ATILE_F (BM * RS)          // 2560 floats
#define NK1 (D_DIM / BK)           // 64
#define NK2 (H_DIM / BK)           // 176
#define NSTG 5                     // pipeline ring depth (prefetch distance 3)

#define STG1_F (3 * ATILE_F)                   // A + B1 + B2
#define STG2_F (2 * ATILE_F)                   // A + B
#define SMEM1_BYTES (NSTG * STG1_F * 4)        // 153600
#define SMEM2_BYTES (NSTG * STG2_F * 4)        // 102400

#define N4X ((long)T_TOK * D_DIM / 4)          // 1048576
#define N4W ((long)E_NUM * H_DIM * D_DIM / 4)  // 5767168

// ---------------- static device scratch --------------------------------------
__device__ float g_xc [(size_t)T_TOK * D_DIM];
__device__ float g_W1c[(size_t)E_NUM * H_DIM * D_DIM];
__device__ float g_W2c[(size_t)E_NUM * H_DIM * D_DIM];
__device__ float g_W3c[(size_t)E_NUM * D_DIM * H_DIM];
__device__ float g_Hh [(size_t)E_NUM * CAP * H_DIM];
__device__ float g_Y  [(size_t)E_NUM * CAP * D_DIM];
__device__ int   g_tok[E_NUM * CAP];
__device__ float g_wgt[E_NUM * CAP];
__device__ int   g_cnt[E_NUM];
__device__ int   g_slot[T_TOK * 2];

// ---------------- helpers -----------------------------------------------------
__device__ __forceinline__ uint32_t s2u(const void* p) {
    uint32_t a;
    asm("{ .reg .u64 t; cvta.to.shared.u64 t, %1; cvt.u32.u64 %0, t; }" : "=r"(a) : "l"(p));
    return a;
}

#define CPA16(s, g) asm volatile("cp.async.cg.shared.global [%0], [%1], 16;" :: "r"(s), "l"(g))
#define CPA_COMMIT() asm volatile("cp.async.commit_group;" ::: "memory")
#define CPA_WAIT(n)  asm volatile("cp.async.wait_group %0;" :: "n"(n) : "memory")

// ldmatrix x4: four 8x8-b32 quadrants (as 8x16 b16 tiles)
#define LDSM_X4(r, addr)                                                          \
    asm volatile("ldmatrix.sync.aligned.m8n8.x4.shared.b16 {%0,%1,%2,%3}, [%4];"  \
        : "=r"((r)[0]), "=r"((r)[1]), "=r"((r)[2]), "=r"((r)[3]) : "r"(addr))

// m16n8k8 tf32 MMA, fp32 accum
#define MMA_TF32(d, a, b)                                                         \
    asm volatile(                                                                 \
        "mma.sync.aligned.m16n8k8.row.col.f32.tf32.tf32.f32 "                     \
        "{%0,%1,%2,%3},{%4,%5,%6,%7},{%8,%9},{%0,%1,%2,%3};"                      \
        : "+f"((d)[0]), "+f"((d)[1]), "+f"((d)[2]), "+f"((d)[3])                  \
        : "r"((a)[0]), "r"((a)[1]), "r"((a)[2]), "r"((a)[3]),                     \
          "r"((b)[0]), "r"((b)[1]))

// RN-even round fp32 -> tf32 bit pattern
__device__ __forceinline__ uint32_t tf32r(uint32_t u) {
    uint32_t l = (u >> 13) & 1u;
    return (u + 0xFFFu + l) & 0xFFFFE000u;
}

// ---------------- fused pre-rounding pass (x, W1, W2, W3) --------------------
// 2 float4 per thread for higher MLP.
__global__ void k_round_all(const float4* __restrict__ x,
                            const float4* __restrict__ W1,
                            const float4* __restrict__ W2,
                            const float4* __restrict__ W3,
                            float4* __restrict__ xc,
                            float4* __restrict__ w1c,
                            float4* __restrict__ w2c,
                            float4* __restrict__ w3c) {
    const long total = N4X + 3 * N4W;
    long base = (long)blockIdx.x * 512 + threadIdx.x;
#pragma unroll
    for (int r = 0; r < 2; r++) {
        long i = base + r * 256;
        if (i >= total) return;
        const float4* s;
        float4* d;
        long off;
        if (i < N4X) { s = x; d = xc; off = i; }
        else {
            long w = i - N4X;
            if (w < N4W)          { s = W1; d = w1c; off = w; }
            else if (w < 2 * N4W) { s = W2; d = w2c; off = w - N4W; }
            else                  { s = W3; d = w3c; off = w - 2 * N4W; }
        }
        float4 v = s[off];
        float4 o;
        o.x = __uint_as_float(tf32r(__float_as_uint(v.x)));
        o.y = __uint_as_float(tf32r(__float_as_uint(v.y)));
        o.z = __uint_as_float(tf32r(__float_as_uint(v.z)));
        o.w = __uint_as_float(tf32r(__float_as_uint(v.w)));
        d[off] = o;
    }
}

// ---------------- counters / gating / combine --------------------------------
__global__ void k_zero() {
    if (threadIdx.x < E_NUM) g_cnt[threadIdx.x] = 0;
}

__global__ void k_gate(const float* __restrict__ x, const float* __restrict__ Wg) {
    int t = blockIdx.x * (blockDim.x >> 5) + (threadIdx.x >> 5);
    int lane = threadIdx.x & 31;
    if (t >= T_TOK) return;
    const float4* xr = (const float4*)(x + (size_t)t * D_DIM);
    float acc[E_NUM];
#pragma unroll
    for (int e = 0; e < E_NUM; e++) acc[e] = 0.f;
    for (int i = lane; i < D_DIM / 4; i += 32) {
        float4 xv = xr[i];
#pragma unroll
        for (int e = 0; e < E_NUM; e++) {
            float4 wv = ((const float4*)(Wg + (size_t)e * D_DIM))[i];
            acc[e] += xv.x * wv.x + xv.y * wv.y + xv.z * wv.z + xv.w * wv.w;
        }
    }
#pragma unroll
    for (int e = 0; e < E_NUM; e++)
#pragma unroll
        for (int o = 16; o > 0; o >>= 1)
            acc[e] += __shfl_xor_sync(0xffffffffu, acc[e], o);
    if (lane == 0) {
        int e0 = 0; float v0 = acc[0];
#pragma unroll
        for (int e = 1; e < E_NUM; e++) if (acc[e] > v0) { v0 = acc[e]; e0 = e; }
        int e1 = -1; float v1 = -INFINITY;
#pragma unroll
        for (int e = 0; e < E_NUM; e++)
            if (e != e0 && acc[e] > v1) { v1 = acc[e]; e1 = e; }
        int i0 = atomicAdd(&g_cnt[e0], 1);
        g_tok[e0 * CAP + i0] = t; g_wgt[e0 * CAP + i0] = v0;
        g_slot[t * 2 + 0] = e0 * CAP + i0;
        int i1 = atomicAdd(&g_cnt[e1], 1);
        g_tok[e1 * CAP + i1] = t; g_wgt[e1 * CAP + i1] = v1;
        g_slot[t * 2 + 1] = e1 * CAP + i1;
    }
}

__global__ void k_combine(float* __restrict__ out) {
    int idx = blockIdx.x * 256 + threadIdx.x;
    int t = idx >> 8;
    int c = idx & 255;
    int s0 = g_slot[t * 2 + 0];
    int s1 = g_slot[t * 2 + 1];
    const float4* Y4 = (const float4*)g_Y;
    float4 a = Y4[(size_t)s0 * (D_DIM / 4) + c];
    float4 b = Y4[(size_t)s1 * (D_DIM / 4) + c];
    float4 o; o.x = a.x + b.x; o.y = a.y + b.y; o.z = a.z + b.z; o.w = a.w + b.w;
    ((float4*)out)[idx] = o;
}

// ---------------- GEMM1: Hh = silu(X W1^T) * (X W2^T) ------------------------
// R7 geometry: 256 threads, 8 warps, warp tile 64x32 dual, occ 1.
// 5-stage cp.async ring, prefetch distance 3, one barrier per 2 k-iters.
// ks order staggered by warp parity to de-phase LDSM bursts.
__global__ __launch_bounds__(256, 1)
void k_ffn1() {
    int e  = blockIdx.x >> 5;
    int m0 = (blockIdx.x & 31) * BM;
    int cnt = g_cnt[e];
    if (m0 >= cnt) return;
    int n0 = blockIdx.y * BN;

    extern __shared__ float sm[];

    int tid  = threadIdx.x;
    int wid  = tid >> 5, lane = tid & 31;
    int wm0  = (wid & 1) * 64;
    int wn0  = (wid >> 1) * 32;
    int grp  = lane >> 2, tg = lane & 3;
    int kflip = wid & 1;               // stagger: odd warps do ks=1 first

    // ldmatrix lane geometry
    int lt = lane >> 3, lr = lane & 7;
    uint32_t smb = s2u(sm);
    uint32_t aAdr = smb + (uint32_t)((wm0 + (lt & 1) * 8 + lr) * RS + (lt >> 1) * 4) * 4u;
    uint32_t bAdr = smb + (uint32_t)((wn0 + (lt >> 1) * 8 + lr) * RS + (lt & 1) * 4) * 4u;

    // loader geometry: thread -> (row = tid/2, col base = (tid&1)*8)
    int lrow = tid >> 1;
    int lc   = (tid & 1) * 8;
    int tok  = g_tok[e * CAP + m0 + lrow];
    tok = min(max(tok, 0), T_TOK - 1);
    const float* aS  = g_xc  + (size_t)tok * D_DIM + lc;
    const float* b1S = g_W1c + ((size_t)e * H_DIM + n0 + lrow) * D_DIM + lc;
    const float* b2S = g_W2c + ((size_t)e * H_DIM + n0 + lrow) * D_DIM + lc;
    uint32_t dst = smb + (uint32_t)(lrow * RS + lc) * 4u;

#define LOAD1(k, stg) do {                                                      \
        int kc = (k) * BK;                                                      \
        uint32_t d0 = dst + (uint32_t)(stg) * STG1_F * 4u;                      \
        CPA16(d0,                  aS  + kc); CPA16(d0 + 16,                  aS  + kc + 4); \
        CPA16(d0 + ATILE_F * 4,    b1S + kc); CPA16(d0 + ATILE_F * 4 + 16,    b1S + kc + 4); \
        CPA16(d0 + 2 * ATILE_F * 4, b2S + kc); CPA16(d0 + 2 * ATILE_F * 4 + 16, b2S + kc + 4); \
    } while (0)

    float accG[4][4][4], accU[4][4][4];
#pragma unroll
    for (int i = 0; i < 4; i++)
#pragma unroll
        for (int j = 0; j < 4; j++)
#pragma unroll
            for (int r = 0; r < 4; r++) { accG[i][j][r] = 0.f; accU[i][j][r] = 0.f; }

#define COMPUTE1(cs) do {                                                       \
        uint32_t sA  = aAdr + (uint32_t)((cs) * STG1_F) * 4u;                   \
        uint32_t sB1 = bAdr + (uint32_t)((cs) * STG1_F + ATILE_F) * 4u;         \
        uint32_t sB2 = sB1 + (uint32_t)(ATILE_F) * 4u;                          \
        _Pragma("unroll")                                                       \
        for (int kk = 0; kk < 2; kk++) {                                        \
            int ks = kk ^ kflip;                                                \
            uint32_t a[4][4];                                                   \
            _Pragma("unroll")                                                   \
            for (int mt = 0; mt < 4; mt++)                                      \
                LDSM_X4(a[mt], sA + (uint32_t)(mt * 16 * RS) * 4u + (uint32_t)(ks * 32)); \
            uint32_t b1[2][4], b2[2][4];                                        \
            _Pragma("unroll")                                                   \
            for (int p = 0; p < 2; p++) {                                       \
                LDSM_X4(b1[p], sB1 + (uint32_t)(p * 16 * RS) * 4u + (uint32_t)(ks * 32)); \
                LDSM_X4(b2[p], sB2 + (uint32_t)(p * 16 * RS) * 4u + (uint32_t)(ks * 32)); \
            }                                                                   \
            _Pragma("unroll")                                                   \
            for (int mt = 0; mt < 4; mt++)                                      \
                _Pragma("unroll")                                               \
                for (int nt = 0; nt < 4; nt++) {                                \
                    MMA_TF32(accG[mt][nt], a[mt], &b1[nt >> 1][(nt & 1) * 2]);  \
                    MMA_TF32(accU[mt][nt], a[mt], &b2[nt >> 1][(nt & 1) * 2]);  \
                }                                                               \
        }                                                                       \
    } while (0)

    LOAD1(0, 0); CPA_COMMIT();
    LOAD1(1, 1); CPA_COMMIT();
    LOAD1(2, 2); CPA_COMMIT();

    int cs = 0, ls = 3;
    for (int k = 0; k < NK1; k += 2) {
        CPA_WAIT(1);                 // groups <= k+2 done: stages <= k+1 complete
        __syncthreads();             // publish stages k, k+1; retire reads <= k-1
        if (k + 3 < NK1) LOAD1(k + 3, ls);
        CPA_COMMIT();
        if (++ls == NSTG) ls = 0;
        COMPUTE1(cs);                // stage k
        if (++cs == NSTG) cs = 0;
        if (k + 4 < NK1) LOAD1(k + 4, ls);
        CPA_COMMIT();
        if (++ls == NSTG) ls = 0;
        COMPUTE1(cs);                // stage k+1
        if (++cs == NSTG) cs = 0;
    }
#undef LOAD1
#undef COMPUTE1

    // epilogue: h = tf32(silu(g) * u)
#pragma unroll
    for (int mt = 0; mt < 4; mt++) {
#pragma unroll
        for (int nt = 0; nt < 4; nt++) {
            int r0 = m0 + wm0 + mt * 16 + grp;
            int cc = n0 + wn0 + nt * 8 + 2 * tg;
#pragma unroll
            for (int h = 0; h < 2; h++) {
                int row = r0 + h * 8;
                if (row < cnt) {
                    float gv0 = accG[mt][nt][2 * h + 0], uv0 = accU[mt][nt][2 * h + 0];
                    float gv1 = accG[mt][nt][2 * h + 1], uv1 = accU[mt][nt][2 * h + 1];
                    float h0 = (gv0 / (1.f + __expf(-gv0))) * uv0;
                    float h1 = (gv1 / (1.f + __expf(-gv1))) * uv1;
                    float2 o;
                    o.x = __uint_as_float(tf32r(__float_as_uint(h0)));
                    o.y = __uint_as_float(tf32r(__float_as_uint(h1)));
                    *(float2*)&g_Hh[((size_t)e * CAP + row) * H_DIM + cc] = o;
                }
            }
        }
    }
}

// ---------------- GEMM2: Y = wgt * (Hh @ W3[e]^T) ----------------------------
// 256 threads, warp tile 64x32, occ 2; ks stagger added.
__global__ __launch_bounds__(256, 2)
void k_ffn2() {
    int e  = blockIdx.x >> 5;
    int m0 = (blockIdx.x & 31) * BM;
    int cnt = g_cnt[e];
    if (m0 >= cnt) return;
    int n0 = blockIdx.y * BN;

    extern __shared__ float sm[];

    int tid  = threadIdx.x;
    int wid  = tid >> 5, lane = tid & 31;
    int wm0  = (wid & 1) * 64;
    int wn0  = (wid >> 1) * 32;
    int grp  = lane >> 2, tg = lane & 3;
    int kflip = wid & 1;

    int lt = lane >> 3, lr = lane & 7;
    uint32_t smb = s2u(sm);
    uint32_t aAdr = smb + (uint32_t)((wm0 + (lt & 1) * 8 + lr) * RS + (lt >> 1) * 4) * 4u;
    uint32_t bAdr = smb + (uint32_t)((wn0 + (lt >> 1) * 8 + lr) * RS + (lt & 1) * 4) * 4u;

    int lrow = tid >> 1;
    int lc   = (tid & 1) * 8;
    const float* aS = g_Hh  + ((size_t)e * CAP + m0 + lrow) * H_DIM + lc;
    const float* bS = g_W3c + ((size_t)e * D_DIM + n0 + lrow) * H_DIM + lc;
    uint32_t dst = smb + (uint32_t)(lrow * RS + lc) * 4u;

#define LOAD2(k, stg) do {                                                      \
        int kc = (k) * BK;                                                      \
        uint32_t d0 = dst + (uint32_t)(stg) * STG2_F * 4u;                      \
        CPA16(d0,               aS + kc); CPA16(d0 + 16,               aS + kc + 4); \
        CPA16(d0 + ATILE_F * 4, bS + kc); CPA16(d0 + ATILE_F * 4 + 16, bS + kc + 4); \
    } while (0)

    float acc[4][4][4];
#pragma unroll
    for (int i = 0; i < 4; i++)
#pragma unroll
        for (int j = 0; j < 4; j++)
#pragma unroll
            for (int r = 0; r < 4; r++) acc[i][j][r] = 0.f;

#define COMPUTE2(cs) do {                                                       \
        uint32_t sA = aAdr + (uint32_t)((cs) * STG2_F) * 4u;                    \
        uint32_t sB = bAdr + (uint32_t)((cs) * STG2_F + ATILE_F) * 4u;          \
        _Pragma("unroll")                                                       \
        for (int kk = 0; kk < 2; kk++) {                                        \
            int ks = kk ^ kflip;                                                \
            uint32_t a[4][4];                                                   \
            _Pragma("unroll")                                                   \
            for (int mt = 0; mt < 4; mt++)                                      \
                LDSM_X4(a[mt], sA + (uint32_t)(mt * 16 * RS) * 4u + (uint32_t)(ks * 32)); \
            uint32_t b[2][4];                                                   \
            _Pragma("unroll")                                                   \
            for (int p = 0; p < 2; p++)                                         \
                LDSM_X4(b[p], sB + (uint32_t)(p * 16 * RS) * 4u + (uint32_t)(ks * 32)); \
            _Pragma("unroll")                                                   \
            for (int mt = 0; mt < 4; mt++)                                      \
                _Pragma("unroll")                                               \
                for (int nt = 0; nt < 4; nt++)                                  \
                    MMA_TF32(acc[mt][nt], a[mt], &b[nt >> 1][(nt & 1) * 2]);    \
        }                                                                       \
    } while (0)

    LOAD2(0, 0); CPA_COMMIT();
    LOAD2(1, 1); CPA_COMMIT();
    LOAD2(2, 2); CPA_COMMIT();

    int cs = 0, ls = 3;
    for (int k = 0; k < NK2; k += 2) {
        CPA_WAIT(1);
        __syncthreads();
        if (k + 3 < NK2) LOAD2(k + 3, ls);
        CPA_COMMIT();
        if (++ls == NSTG) ls = 0;
        COMPUTE2(cs);
        if (++cs == NSTG) cs = 0;
        if (k + 4 < NK2) LOAD2(k + 4, ls);
        CPA_COMMIT();
        if (++ls == NSTG) ls = 0;
        COMPUTE2(cs);
        if (++cs == NSTG) cs = 0;
    }
#undef LOAD2
#undef COMPUTE2

#pragma unroll
    for (int mt = 0; mt < 4; mt++) {
        int r0 = m0 + wm0 + mt * 16 + grp;
#pragma unroll
        for (int h = 0; h < 2; h++) {
            int row = r0 + h * 8;
            if (row < cnt) {
                float w = g_wgt[e * CAP + row];
#pragma unroll
                for (int nt = 0; nt < 4; nt++) {
                    int cc = n0 + wn0 + nt * 8 + 2 * tg;
                    float2 o;
                    o.x = acc[mt][nt][2 * h + 0] * w;
                    o.y = acc[mt][nt][2 * h + 1] * w;
                    *(float2*)&g_Y[((size_t)e * CAP + row) * D_DIM + cc] = o;
                }
            }
        }
    }
}

// -----------------------------------------------------------------------------
extern "C" void kernel_launch(void* const* d_in, const int* in_sizes, int n_in,
                              void* d_out, int out_size) {
    const float* x  = (const float*)d_in[0];
    const float* Wg = (const float*)d_in[1];
    const float* W1 = (const float*)d_in[2];
    const float* W2 = (const float*)d_in[3];
    const float* W3 = (const float*)d_in[4];
    float* out = (float*)d_out;

    cudaFuncSetAttribute(k_ffn1, cudaFuncAttributeMaxDynamicSharedMemorySize, SMEM1_BYTES);
    cudaFuncSetAttribute(k_ffn2, cudaFuncAttributeMaxDynamicSharedMemorySize, SMEM2_BYTES);

    void *p_xc, *p_w1, *p_w2, *p_w3;
    cudaGetSymbolAddress(&p_xc, g_xc);
    cudaGetSymbolAddress(&p_w1, g_W1c);
    cudaGetSymbolAddress(&p_w2, g_W2c);
    cudaGetSymbolAddress(&p_w3, g_W3c);

    long n4_total = N4X + 3 * N4W;                     // 18350080
    int  nblk     = (int)((n4_total + 511) / 512);     // 35840 (2 f4/thread)

    k_round_all<<<nblk, 256>>>((const float4*)x,  (const float4*)W1,
                               (const float4*)W2, (const float4*)W3,
                               (float4*)p_xc, (float4*)p_w1,
                               (float4*)p_w2, (float4*)p_w3);          // 1
    k_zero<<<1, 32>>>();                                               // 2
    k_gate<<<T_TOK / 8, 256>>>(x, Wg);                                 // 3

    dim3 g1(E_NUM * (CAP / BM), H_DIM / BN);   // (256, 22)
    k_ffn1<<<g1, 256, SMEM1_BYTES>>>();                                // 4 <- profile target
    dim3 g2(E_NUM * (CAP / BM), D_DIM / BN);   // (256, 8)
    k_ffn2<<<g2, 256, SMEM2_BYTES>>>();                                // 5 <- profile target

    k_combine<<<(T_TOK * D_DIM / 4) / 256, 256>>>(out);                // 6
}

// round 11
// speedup vs baseline: 2.4784x; 1.8092x over previous
#include <cuda_runtime.h>
#include <cuda_fp16.h>
#include <cstdint>
#include <math.h>

// ---------------- problem constants ------------------------------------------
#define T_TOK 4096
#define D_DIM 1024
#define H_DIM 2816
#define E_NUM 8
#define CAP   4096

#define BM 128
#define BN 128
#define BK 32                      // K elems (halves) per stage: 64B data/row
#define RSB 80                     // padded smem row stride in BYTES (conflict-free)
#define ATILE_B (BM * RSB)         // 10240 bytes per 128-row tile
#define NK1 (D_DIM / BK)           // 32
#define NK2 (H_DIM / BK)           // 88
#define NSTG 5                     // pipeline ring depth (prefetch distance 3)

#define STG1_B (3 * ATILE_B)                   // A + B1 + B2 = 30720
#define STG2_B (2 * ATILE_B)                   // A + B = 20480
#define SMEM1_BYTES (NSTG * STG1_B)            // 153600
#define SMEM2_BYTES (NSTG * STG2_B)            // 102400

#define N4X ((long)T_TOK * D_DIM / 4)          // 1048576
#define N4W ((long)E_NUM * H_DIM * D_DIM / 4)  // 5767168

// ---------------- static device scratch --------------------------------------
__device__ __half g_xch[(size_t)T_TOK * D_DIM];
__device__ __half g_W1h[(size_t)E_NUM * H_DIM * D_DIM];
__device__ __half g_W2h[(size_t)E_NUM * H_DIM * D_DIM];
__device__ __half g_W3h[(size_t)E_NUM * D_DIM * H_DIM];
__device__ __half g_Hh [(size_t)E_NUM * CAP * H_DIM];
__device__ float  g_Y  [(size_t)E_NUM * CAP * D_DIM];
__device__ int    g_tok[E_NUM * CAP];
__device__ float  g_wgt[E_NUM * CAP];
__device__ int    g_cnt[E_NUM];
__device__ int    g_slot[T_TOK * 2];

// ---------------- helpers -----------------------------------------------------
__device__ __forceinline__ uint32_t s2u(const void* p) {
    uint32_t a;
    asm("{ .reg .u64 t; cvta.to.shared.u64 t, %1; cvt.u32.u64 %0, t; }" : "=r"(a) : "l"(p));
    return a;
}

#define CPA16(s, g) asm volatile("cp.async.cg.shared.global [%0], [%1], 16;" :: "r"(s), "l"(g))
#define CPA_COMMIT() asm volatile("cp.async.commit_group;" ::: "memory")
#define CPA_WAIT(n)  asm volatile("cp.async.wait_group %0;" :: "n"(n) : "memory")

// ldmatrix x4: four 8x8 b16 matrices
#define LDSM_X4(r, addr)                                                          \
    asm volatile("ldmatrix.sync.aligned.m8n8.x4.shared.b16 {%0,%1,%2,%3}, [%4];"  \
        : "=r"((r)[0]), "=r"((r)[1]), "=r"((r)[2]), "=r"((r)[3]) : "r"(addr))

// m16n8k16 fp16 MMA, fp32 accum
#define MMA_F16(d, a, b)                                                          \
    asm volatile(                                                                 \
        "mma.sync.aligned.m16n8k16.row.col.f32.f16.f16.f32 "                      \
        "{%0,%1,%2,%3},{%4,%5,%6,%7},{%8,%9},{%0,%1,%2,%3};"                      \
        : "+f"((d)[0]), "+f"((d)[1]), "+f"((d)[2]), "+f"((d)[3])                  \
        : "r"((a)[0]), "r"((a)[1]), "r"((a)[2]), "r"((a)[3]),                     \
          "r"((b)[0]), "r"((b)[1]))

// ---------------- conversion pass fp32 -> fp16 (x, W1, W2, W3) ---------------
__global__ void k_round_all(const float4* __restrict__ x,
                            const float4* __restrict__ W1,
                            const float4* __restrict__ W2,
                            const float4* __restrict__ W3,
                            __half2* __restrict__ xc,
                            __half2* __restrict__ w1c,
                            __half2* __restrict__ w2c,
                            __half2* __restrict__ w3c) {
    const long total = N4X + 3 * N4W;
    long base = (long)blockIdx.x * 512 + threadIdx.x;
#pragma unroll
    for (int r = 0; r < 2; r++) {
        long i = base + r * 256;
        if (i >= total) return;
        const float4* s;
        __half2* d;
        long off;
        if (i < N4X) { s = x; d = xc; off = i; }
        else {
            long w = i - N4X;
            if (w < N4W)          { s = W1; d = w1c; off = w; }
            else if (w < 2 * N4W) { s = W2; d = w2c; off = w - N4W; }
            else                  { s = W3; d = w3c; off = w - 2 * N4W; }
        }
        float4 v = s[off];
        d[off * 2 + 0] = __floats2half2_rn(v.x, v.y);
        d[off * 2 + 1] = __floats2half2_rn(v.z, v.w);
    }
}

// ---------------- counters / gating / combine --------------------------------
__global__ void k_zero() {
    if (threadIdx.x < E_NUM) g_cnt[threadIdx.x] = 0;
}

__global__ void k_gate(const float* __restrict__ x, const float* __restrict__ Wg) {
    int t = blockIdx.x * (blockDim.x >> 5) + (threadIdx.x >> 5);
    int lane = threadIdx.x & 31;
    if (t >= T_TOK) return;
    const float4* xr = (const float4*)(x + (size_t)t * D_DIM);
    float acc[E_NUM];
#pragma unroll
    for (int e = 0; e < E_NUM; e++) acc[e] = 0.f;
    for (int i = lane; i < D_DIM / 4; i += 32) {
        float4 xv = xr[i];
#pragma unroll
        for (int e = 0; e < E_NUM; e++) {
            float4 wv = ((const float4*)(Wg + (size_t)e * D_DIM))[i];
            acc[e] += xv.x * wv.x + xv.y * wv.y + xv.z * wv.z + xv.w * wv.w;
        }
    }
#pragma unroll
    for (int e = 0; e < E_NUM; e++)
#pragma unroll
        for (int o = 16; o > 0; o >>= 1)
            acc[e] += __shfl_xor_sync(0xffffffffu, acc[e], o);
    if (lane == 0) {
        int e0 = 0; float v0 = acc[0];
#pragma unroll
        for (int e = 1; e < E_NUM; e++) if (acc[e] > v0) { v0 = acc[e]; e0 = e; }
        int e1 = -1; float v1 = -INFINITY;
#pragma unroll
        for (int e = 0; e < E_NUM; e++)
            if (e != e0 && acc[e] > v1) { v1 = acc[e]; e1 = e; }
        int i0 = atomicAdd(&g_cnt[e0], 1);
        g_tok[e0 * CAP + i0] = t; g_wgt[e0 * CAP + i0] = v0;
        g_slot[t * 2 + 0] = e0 * CAP + i0;
        int i1 = atomicAdd(&g_cnt[e1], 1);
        g_tok[e1 * CAP + i1] = t; g_wgt[e1 * CAP + i1] = v1;
        g_slot[t * 2 + 1] = e1 * CAP + i1;
    }
}

__global__ void k_combine(float* __restrict__ out) {
    int idx = blockIdx.x * 256 + threadIdx.x;
    int t = idx >> 8;
    int c = idx & 255;
    int s0 = g_slot[t * 2 + 0];
    int s1 = g_slot[t * 2 + 1];
    const float4* Y4 = (const float4*)g_Y;
    float4 a = Y4[(size_t)s0 * (D_DIM / 4) + c];
    float4 b = Y4[(size_t)s1 * (D_DIM / 4) + c];
    float4 o; o.x = a.x + b.x; o.y = a.y + b.y; o.z = a.z + b.z; o.w = a.w + b.w;
    ((float4*)out)[idx] = o;
}

// ---------------- GEMM1: Hh = silu(X W1^T) * (X W2^T), fp16 ------------------
// 128x128 dual tile, 256 threads, warp tile 64x32, occ 1.
// 5-stage cp.async ring (BK=32), prefetch distance 3, barrier per 2 iters.
__global__ __launch_bounds__(256, 1)
void k_ffn1() {
    int e  = blockIdx.x >> 5;
    int m0 = (blockIdx.x & 31) * BM;
    int cnt = g_cnt[e];
    if (m0 >= cnt) return;
    int n0 = blockIdx.y * BN;

    extern __shared__ char sm[];

    int tid  = threadIdx.x;
    int wid  = tid >> 5, lane = tid & 31;
    int wm0  = (wid & 1) * 64;
    int wn0  = (wid >> 1) * 32;
    int grp  = lane >> 2, tg = lane & 3;

    // ldmatrix lane geometry (byte-identical to tf32 layout; elements are halves)
    int lt = lane >> 3, lr = lane & 7;
    uint32_t smb = s2u(sm);
    uint32_t aAdr = smb + (uint32_t)((wm0 + (lt & 1) * 8 + lr) * RSB + (lt >> 1) * 16);
    uint32_t bAdr = smb + (uint32_t)((wn0 + (lt >> 1) * 8 + lr) * RSB + (lt & 1) * 16);

    // loader: thread -> (row = tid/2, 32B half-row = tid&1), 2 CPA16 per tile
    int lrow = tid >> 1;
    int lch  = (tid & 1) * 16;   // half offset within row
    int tok  = g_tok[e * CAP + m0 + lrow];
    tok = min(max(tok, 0), T_TOK - 1);
    const __half* aS  = g_xch + (size_t)tok * D_DIM + lch;
    const __half* b1S = g_W1h + ((size_t)e * H_DIM + n0 + lrow) * D_DIM + lch;
    const __half* b2S = g_W2h + ((size_t)e * H_DIM + n0 + lrow) * D_DIM + lch;
    uint32_t dst = smb + (uint32_t)(lrow * RSB + (tid & 1) * 32);

#define LOAD1(k, stg) do {                                                      \
        int kc = (k) * BK;                                                      \
        uint32_t d0 = dst + (uint32_t)(stg) * STG1_B;                           \
        CPA16(d0,               aS  + kc); CPA16(d0 + 16,               aS  + kc + 8); \
        CPA16(d0 + ATILE_B,     b1S + kc); CPA16(d0 + ATILE_B + 16,     b1S + kc + 8); \
        CPA16(d0 + 2 * ATILE_B, b2S + kc); CPA16(d0 + 2 * ATILE_B + 16, b2S + kc + 8); \
    } while (0)

    float accG[4][4][4], accU[4][4][4];
#pragma unroll
    for (int i = 0; i < 4; i++)
#pragma unroll
        for (int j = 0; j < 4; j++)
#pragma unroll
            for (int r = 0; r < 4; r++) { accG[i][j][r] = 0.f; accU[i][j][r] = 0.f; }

#define COMPUTE1(cs) do {                                                       \
        uint32_t sA  = aAdr + (uint32_t)((cs) * STG1_B);                        \
        uint32_t sB1 = bAdr + (uint32_t)((cs) * STG1_B + ATILE_B);              \
        uint32_t sB2 = sB1 + (uint32_t)ATILE_B;                                 \
        _Pragma("unroll")                                                       \
        for (int ks = 0; ks < 2; ks++) {                                        \
            uint32_t a[4][4];                                                   \
            _Pragma("unroll")                                                   \
            for (int mt = 0; mt < 4; mt++)                                      \
                LDSM_X4(a[mt], sA + (uint32_t)(mt * 16 * RSB + ks * 32));       \
            uint32_t b1[2][4], b2[2][4];                                        \
            _Pragma("unroll")                                                   \
            for (int p = 0; p < 2; p++) {                                       \
                LDSM_X4(b1[p], sB1 + (uint32_t)(p * 16 * RSB + ks * 32));       \
                LDSM_X4(b2[p], sB2 + (uint32_t)(p * 16 * RSB + ks * 32));       \
            }                                                                   \
            _Pragma("unroll")                                                   \
            for (int mt = 0; mt < 4; mt++)                                      \
                _Pragma("unroll")                                               \
                for (int nt = 0; nt < 4; nt++) {                                \
                    MMA_F16(accG[mt][nt], a[mt], &b1[nt >> 1][(nt & 1) * 2]);   \
                    MMA_F16(accU[mt][nt], a[mt], &b2[nt >> 1][(nt & 1) * 2]);   \
                }                                                               \
        }                                                                       \
    } while (0)

    LOAD1(0, 0); CPA_COMMIT();
    LOAD1(1, 1); CPA_COMMIT();
    LOAD1(2, 2); CPA_COMMIT();

    int cs = 0, ls = 3;
    for (int k = 0; k < NK1; k += 2) {
        CPA_WAIT(1);                 // groups <= k+2 done: stages <= k+1 complete
        __syncthreads();             // publish stages k, k+1; retire reads <= k-1
        if (k + 3 < NK1) LOAD1(k + 3, ls);
        CPA_COMMIT();
        if (++ls == NSTG) ls = 0;
        COMPUTE1(cs);                // stage k
        if (++cs == NSTG) cs = 0;
        if (k + 4 < NK1) LOAD1(k + 4, ls);
        CPA_COMMIT();
        if (++ls == NSTG) ls = 0;
        COMPUTE1(cs);                // stage k+1
        if (++cs == NSTG) cs = 0;
    }
#undef LOAD1
#undef COMPUTE1

    // epilogue: h = fp16(silu(g) * u)
#pragma unroll
    for (int mt = 0; mt < 4; mt++) {
#pragma unroll
        for (int nt = 0; nt < 4; nt++) {
            int r0 = m0 + wm0 + mt * 16 + grp;
            int cc = n0 + wn0 + nt * 8 + 2 * tg;
#pragma unroll
            for (int h = 0; h < 2; h++) {
                int row = r0 + h * 8;
                if (row < cnt) {
                    float gv0 = accG[mt][nt][2 * h + 0], uv0 = accU[mt][nt][2 * h + 0];
                    float gv1 = accG[mt][nt][2 * h + 1], uv1 = accU[mt][nt][2 * h + 1];
                    float h0 = (gv0 / (1.f + __expf(-gv0))) * uv0;
                    float h1 = (gv1 / (1.f + __expf(-gv1))) * uv1;
                    *(__half2*)&g_Hh[((size_t)e * CAP + row) * H_DIM + cc] =
                        __floats2half2_rn(h0, h1);
                }
            }
        }
    }
}

// ---------------- GEMM2: Y = wgt * (Hh @ W3[e]^T), fp16 ----------------------
// 256 threads, warp tile 64x32, occ 2.
__global__ __launch_bounds__(256, 2)
void k_ffn2() {
    int e  = blockIdx.x >> 5;
    int m0 = (blockIdx.x & 31) * BM;
    int cnt = g_cnt[e];
    if (m0 >= cnt) return;
    int n0 = blockIdx.y * BN;

    extern __shared__ char sm[];

    int tid  = threadIdx.x;
    int wid  = tid >> 5, lane = tid & 31;
    int wm0  = (wid & 1) * 64;
    int wn0  = (wid >> 1) * 32;
    int grp  = lane >> 2, tg = lane & 3;

    int lt = lane >> 3, lr = lane & 7;
    uint32_t smb = s2u(sm);
    uint32_t aAdr = smb + (uint32_t)((wm0 + (lt & 1) * 8 + lr) * RSB + (lt >> 1) * 16);
    uint32_t bAdr = smb + (uint32_t)((wn0 + (lt >> 1) * 8 + lr) * RSB + (lt & 1) * 16);

    int lrow = tid >> 1;
    int lch  = (tid & 1) * 16;
    const __half* aS = g_Hh  + ((size_t)e * CAP + m0 + lrow) * H_DIM + lch;
    const __half* bS = g_W3h + ((size_t)e * D_DIM + n0 + lrow) * H_DIM + lch;
    uint32_t dst = smb + (uint32_t)(lrow * RSB + (tid & 1) * 32);

#define LOAD2(k, stg) do {                                                      \
        int kc = (k) * BK;                                                      \
        uint32_t d0 = dst + (uint32_t)(stg) * STG2_B;                           \
        CPA16(d0,           aS + kc); CPA16(d0 + 16,           aS + kc + 8);    \
        CPA16(d0 + ATILE_B, bS + kc); CPA16(d0 + ATILE_B + 16, bS + kc + 8);    \
    } while (0)

    float acc[4][4][4];
#pragma unroll
    for (int i = 0; i < 4; i++)
#pragma unroll
        for (int j = 0; j < 4; j++)
#pragma unroll
            for (int r = 0; r < 4; r++) acc[i][j][r] = 0.f;

#define COMPUTE2(cs) do {                                                       \
        uint32_t sA = aAdr + (uint32_t)((cs) * STG2_B);                         \
        uint32_t sB = bAdr + (uint32_t)((cs) * STG2_B + ATILE_B);               \
        _Pragma("unroll")                                                       \
        for (int ks = 0; ks < 2; ks++) {                                        \
            uint32_t a[4][4];                                                   \
            _Pragma("unroll")                                                   \
            for (int mt = 0; mt < 4; mt++)                                      \
                LDSM_X4(a[mt], sA + (uint32_t)(mt * 16 * RSB + ks * 32));       \
            uint32_t b[2][4];                                                   \
            _Pragma("unroll")                                                   \
            for (int p = 0; p < 2; p++)                                         \
                LDSM_X4(b[p], sB + (uint32_t)(p * 16 * RSB + ks * 32));         \
            _Pragma("unroll")                                                   \
            for (int mt = 0; mt < 4; mt++)                                      \
                _Pragma("unroll")                                               \
                for (int nt = 0; nt < 4; nt++)                                  \
                    MMA_F16(acc[mt][nt], a[mt], &b[nt >> 1][(nt & 1) * 2]);     \
        }                                                                       \
    } while (0)

    LOAD2(0, 0); CPA_COMMIT();
    LOAD2(1, 1); CPA_COMMIT();
    LOAD2(2, 2); CPA_COMMIT();

    int cs = 0, ls = 3;
    for (int k = 0; k < NK2; k += 2) {
        CPA_WAIT(1);
        __syncthreads();
        if (k + 3 < NK2) LOAD2(k + 3, ls);
        CPA_COMMIT();
        if (++ls == NSTG) ls = 0;
        COMPUTE2(cs);
        if (++cs == NSTG) cs = 0;
        if (k + 4 < NK2) LOAD2(k + 4, ls);
        CPA_COMMIT();
        if (++ls == NSTG) ls = 0;
        COMPUTE2(cs);
        if (++cs == NSTG) cs = 0;
    }
#undef LOAD2
#undef COMPUTE2

#pragma unroll
    for (int mt = 0; mt < 4; mt++) {
        int r0 = m0 + wm0 + mt * 16 + grp;
#pragma unroll
        for (int h = 0; h < 2; h++) {
            int row = r0 + h * 8;
            if (row < cnt) {
                float w = g_wgt[e * CAP + row];
#pragma unroll
                for (int nt = 0; nt < 4; nt++) {
                    int cc = n0 + wn0 + nt * 8 + 2 * tg;
                    float2 o;
                    o.x = acc[mt][nt][2 * h + 0] * w;
                    o.y = acc[mt][nt][2 * h + 1] * w;
                    *(float2*)&g_Y[((size_t)e * CAP + row) * D_DIM + cc] = o;
                }
            }
        }
    }
}

// -----------------------------------------------------------------------------
extern "C" void kernel_launch(void* const* d_in, const int* in_sizes, int n_in,
                              void* d_out, int out_size) {
    const float* x  = (const float*)d_in[0];
    const float* Wg = (const float*)d_in[1];
    const float* W1 = (const float*)d_in[2];
    const float* W2 = (const float*)d_in[3];
    const float* W3 = (const float*)d_in[4];
    float* out = (float*)d_out;

    cudaFuncSetAttribute(k_ffn1, cudaFuncAttributeMaxDynamicSharedMemorySize, SMEM1_BYTES);
    cudaFuncSetAttribute(k_ffn2, cudaFuncAttributeMaxDynamicSharedMemorySize, SMEM2_BYTES);

    void *p_xc, *p_w1, *p_w2, *p_w3;
    cudaGetSymbolAddress(&p_xc, g_xch);
    cudaGetSymbolAddress(&p_w1, g_W1h);
    cudaGetSymbolAddress(&p_w2, g_W2h);
    cudaGetSymbolAddress(&p_w3, g_W3h);

    long n4_total = N4X + 3 * N4W;                     // 18350080
    int  nblk     = (int)((n4_total + 511) / 512);     // 35840 (2 groups/thread)

    k_round_all<<<nblk, 256>>>((const float4*)x,  (const float4*)W1,
                               (const float4*)W2, (const float4*)W3,
                               (__half2*)p_xc, (__half2*)p_w1,
                               (__half2*)p_w2, (__half2*)p_w3);        // 1
    k_zero<<<1, 32>>>();                                               // 2
    k_gate<<<T_TOK / 8, 256>>>(x, Wg);                                 // 3

    dim3 g1(E_NUM * (CAP / BM), H_DIM / BN);   // (256, 22)
    k_ffn1<<<g1, 256, SMEM1_BYTES>>>();                                // 4 <- profile target
    dim3 g2(E_NUM * (CAP / BM), D_DIM / BN);   // (256, 8)
    k_ffn2<<<g2, 256, SMEM2_BYTES>>>();                                // 5 <- profile target

    k_combine<<<(T_TOK * D_DIM / 4) / 256, 256>>>(out);                // 6
}

// round 13
// speedup vs baseline: 2.5158x; 1.0151x over previous
#include <cuda_runtime.h>
#include <cuda_fp16.h>
#include <cstdint>
#include <math.h>

// ---------------- problem constants ------------------------------------------
#define T_TOK 4096
#define D_DIM 1024
#define H_DIM 2816
#define E_NUM 8
#define CAP   4096

#define BM 128
#define BN 128
#define BK 32                      // K halves per stage: 64B data/row
#define RSB 80                     // padded smem row stride in BYTES
#define ATILE_B (BM * RSB)         // 10240 bytes per 128-row tile
#define NK1 (D_DIM / BK)           // 32
#define NK2 (H_DIM / BK)           // 88
#define NSTG1 6                    // ffn1 ring depth (preload 4)
#define NSTG2 5                    // ffn2 ring depth (preload 3, occ 2)

#define STG1_B (3 * ATILE_B)                   // A + B1 + B2 = 30720
#define STG2_B (2 * ATILE_B)                   // A + B = 20480
#define SMEM1_BYTES (NSTG1 * STG1_B)           // 184320
#define SMEM2_BYTES (NSTG2 * STG2_B)           // 102400

#define N4X ((long)T_TOK * D_DIM / 4)          // 1048576
#define N4W ((long)E_NUM * H_DIM * D_DIM / 4)  // 5767168

// ---------------- static device scratch --------------------------------------
__device__ __half g_xch[(size_t)T_TOK * D_DIM];
__device__ __half g_W1h[(size_t)E_NUM * H_DIM * D_DIM];
__device__ __half g_W2h[(size_t)E_NUM * H_DIM * D_DIM];
__device__ __half g_W3h[(size_t)E_NUM * D_DIM * H_DIM];
__device__ __half g_Hh [(size_t)E_NUM * CAP * H_DIM];
__device__ float  g_Y  [(size_t)E_NUM * CAP * D_DIM];
__device__ int    g_tok[E_NUM * CAP];
__device__ float  g_wgt[E_NUM * CAP];
__device__ int    g_cnt[E_NUM];
__device__ int    g_slot[T_TOK * 2];

// ---------------- helpers -----------------------------------------------------
__device__ __forceinline__ uint32_t s2u(const void* p) {
    uint32_t a;
    asm("{ .reg .u64 t; cvta.to.shared.u64 t, %1; cvt.u32.u64 %0, t; }" : "=r"(a) : "l"(p));
    return a;
}

#define CPA16(s, g) asm volatile("cp.async.cg.shared.global [%0], [%1], 16;" :: "r"(s), "l"(g))
#define CPA_COMMIT() asm volatile("cp.async.commit_group;" ::: "memory")
#define CPA_WAIT(n)  asm volatile("cp.async.wait_group %0;" :: "n"(n) : "memory")

#define LDSM_X4(r, addr)                                                          \
    asm volatile("ldmatrix.sync.aligned.m8n8.x4.shared.b16 {%0,%1,%2,%3}, [%4];"  \
        : "=r"((r)[0]), "=r"((r)[1]), "=r"((r)[2]), "=r"((r)[3]) : "r"(addr))

#define MMA_F16(d, a, b)                                                          \
    asm volatile(                                                                 \
        "mma.sync.aligned.m16n8k16.row.col.f32.f16.f16.f32 "                      \
        "{%0,%1,%2,%3},{%4,%5,%6,%7},{%8,%9},{%0,%1,%2,%3};"                      \
        : "+f"((d)[0]), "+f"((d)[1]), "+f"((d)[2]), "+f"((d)[3])                  \
        : "r"((a)[0]), "r"((a)[1]), "r"((a)[2]), "r"((a)[3]),                     \
          "r"((b)[0]), "r"((b)[1]))

// ---------------- conversion pass fp32 -> fp16 (x, W1, W2, W3) ---------------
__global__ void k_round_all(const float4* __restrict__ x,
                            const float4* __restrict__ W1,
                            const float4* __restrict__ W2,
                            const float4* __restrict__ W3,
                            __half2* __restrict__ xc,
                            __half2* __restrict__ w1c,
                            __half2* __restrict__ w2c,
                            __half2* __restrict__ w3c) {
    const long total = N4X + 3 * N4W;
    long base = (long)blockIdx.x * 512 + threadIdx.x;
#pragma unroll
    for (int r = 0; r < 2; r++) {
        long i = base + r * 256;
        if (i >= total) return;
        const float4* s;
        __half2* d;
        long off;
        if (i < N4X) { s = x; d = xc; off = i; }
        else {
            long w = i - N4X;
            if (w < N4W)          { s = W1; d = w1c; off = w; }
            else if (w < 2 * N4W) { s = W2; d = w2c; off = w - N4W; }
            else                  { s = W3; d = w3c; off = w - 2 * N4W; }
        }
        float4 v = s[off];
        d[off * 2 + 0] = __floats2half2_rn(v.x, v.y);
        d[off * 2 + 1] = __floats2half2_rn(v.z, v.w);
    }
}

// ---------------- counters / gating / combine --------------------------------
__global__ void k_zero() {
    if (threadIdx.x < E_NUM) g_cnt[threadIdx.x] = 0;
}

__global__ void k_gate(const float* __restrict__ x, const float* __restrict__ Wg) {
    int t = blockIdx.x * (blockDim.x >> 5) + (threadIdx.x >> 5);
    int lane = threadIdx.x & 31;
    if (t >= T_TOK) return;
    const float4* xr = (const float4*)(x + (size_t)t * D_DIM);
    float acc[E_NUM];
#pragma unroll
    for (int e = 0; e < E_NUM; e++) acc[e] = 0.f;
    for (int i = lane; i < D_DIM / 4; i += 32) {
        float4 xv = xr[i];
#pragma unroll
        for (int e = 0; e < E_NUM; e++) {
            float4 wv = ((const float4*)(Wg + (size_t)e * D_DIM))[i];
            acc[e] += xv.x * wv.x + xv.y * wv.y + xv.z * wv.z + xv.w * wv.w;
        }
    }
#pragma unroll
    for (int e = 0; e < E_NUM; e++)
#pragma unroll
        for (int o = 16; o > 0; o >>= 1)
            acc[e] += __shfl_xor_sync(0xffffffffu, acc[e], o);
    if (lane == 0) {
        int e0 = 0; float v0 = acc[0];
#pragma unroll
        for (int e = 1; e < E_NUM; e++) if (acc[e] > v0) { v0 = acc[e]; e0 = e; }
        int e1 = -1; float v1 = -INFINITY;
#pragma unroll
        for (int e = 0; e < E_NUM; e++)
            if (e != e0 && acc[e] > v1) { v1 = acc[e]; e1 = e; }
        int i0 = atomicAdd(&g_cnt[e0], 1);
        g_tok[e0 * CAP + i0] = t; g_wgt[e0 * CAP + i0] = v0;
        g_slot[t * 2 + 0] = e0 * CAP + i0;
        int i1 = atomicAdd(&g_cnt[e1], 1);
        g_tok[e1 * CAP + i1] = t; g_wgt[e1 * CAP + i1] = v1;
        g_slot[t * 2 + 1] = e1 * CAP + i1;
    }
}

__global__ void k_combine(float* __restrict__ out) {
    int idx = blockIdx.x * 256 + threadIdx.x;
    int t = idx >> 8;
    int c = idx & 255;
    int s0 = g_slot[t * 2 + 0];
    int s1 = g_slot[t * 2 + 1];
    const float4* Y4 = (const float4*)g_Y;
    float4 a = Y4[(size_t)s0 * (D_DIM / 4) + c];
    float4 b = Y4[(size_t)s1 * (D_DIM / 4) + c];
    float4 o; o.x = a.x + b.x; o.y = a.y + b.y; o.z = a.z + b.z; o.w = a.w + b.w;
    ((float4*)out)[idx] = o;
}

// ---------------- GEMM1: Hh = silu(X W1^T) * (X W2^T), fp16 ------------------
// 128x128 dual tile, 256 threads, warp tile 64x32, occ 1.
// 6-stage cp.async ring, preload 4, barrier per 2 stages.
// Fragment double-buffering across the 4 ks-steps between barriers.
__global__ __launch_bounds__(256, 1)
void k_ffn1() {
    int e  = blockIdx.x >> 5;
    int m0 = (blockIdx.x & 31) * BM;
    int cnt = g_cnt[e];
    if (m0 >= cnt) return;
    int n0 = blockIdx.y * BN;

    extern __shared__ char sm[];

    int tid  = threadIdx.x;
    int wid  = tid >> 5, lane = tid & 31;
    int wm0  = (wid & 1) * 64;
    int wn0  = (wid >> 1) * 32;
    int grp  = lane >> 2, tg = lane & 3;

    int lt = lane >> 3, lr = lane & 7;
    uint32_t smb = s2u(sm);
    uint32_t aAdr = smb + (uint32_t)((wm0 + (lt & 1) * 8 + lr) * RSB + (lt >> 1) * 16);
    uint32_t bAdr = smb + (uint32_t)((wn0 + (lt >> 1) * 8 + lr) * RSB + (lt & 1) * 16);

    int lrow = tid >> 1;
    int lch  = (tid & 1) * 16;
    int tok  = g_tok[e * CAP + m0 + lrow];
    tok = min(max(tok, 0), T_TOK - 1);
    const __half* aS  = g_xch + (size_t)tok * D_DIM + lch;
    const __half* b1S = g_W1h + ((size_t)e * H_DIM + n0 + lrow) * D_DIM + lch;
    const __half* b2S = g_W2h + ((size_t)e * H_DIM + n0 + lrow) * D_DIM + lch;
    uint32_t dst = smb + (uint32_t)(lrow * RSB + (tid & 1) * 32);

#define LOAD1(k, stg) do {                                                      \
        int kc = (k) * BK;                                                      \
        uint32_t d0 = dst + (uint32_t)(stg) * STG1_B;                           \
        CPA16(d0,               aS  + kc); CPA16(d0 + 16,               aS  + kc + 8); \
        CPA16(d0 + ATILE_B,     b1S + kc); CPA16(d0 + ATILE_B + 16,     b1S + kc + 8); \
        CPA16(d0 + 2 * ATILE_B, b2S + kc); CPA16(d0 + 2 * ATILE_B + 16, b2S + kc + 8); \
    } while (0)

    float accG[4][4][4], accU[4][4][4];
#pragma unroll
    for (int i = 0; i < 4; i++)
#pragma unroll
        for (int j = 0; j < 4; j++)
#pragma unroll
            for (int r = 0; r < 4; r++) { accG[i][j][r] = 0.f; accU[i][j][r] = 0.f; }

    // rolling fragment buffers
    uint32_t af[2][4][4], b1f[2][2][4], b2f[2][2][4];

#define LDSM_STEP(buf, stg, ks) do {                                            \
        uint32_t sA  = aAdr + (uint32_t)((stg) * STG1_B + (ks) * 32);           \
        uint32_t sB1 = bAdr + (uint32_t)((stg) * STG1_B + ATILE_B + (ks) * 32); \
        uint32_t sB2 = sB1 + (uint32_t)ATILE_B;                                 \
        _Pragma("unroll")                                                       \
        for (int mt = 0; mt < 4; mt++)                                          \
            LDSM_X4(af[buf][mt], sA + (uint32_t)(mt * 16 * RSB));               \
        _Pragma("unroll")                                                       \
        for (int p = 0; p < 2; p++) {                                           \
            LDSM_X4(b1f[buf][p], sB1 + (uint32_t)(p * 16 * RSB));               \
            LDSM_X4(b2f[buf][p], sB2 + (uint32_t)(p * 16 * RSB));               \
        }                                                                       \
    } while (0)

#define MMA_STEP(buf) do {                                                      \
        _Pragma("unroll")                                                       \
        for (int mt = 0; mt < 4; mt++)                                          \
            _Pragma("unroll")                                                   \
            for (int nt = 0; nt < 4; nt++) {                                    \
                MMA_F16(accG[mt][nt], af[buf][mt], &b1f[buf][nt >> 1][(nt & 1) * 2]); \
                MMA_F16(accU[mt][nt], af[buf][mt], &b2f[buf][nt >> 1][(nt & 1) * 2]); \
            }                                                                   \
    } while (0)

    LOAD1(0, 0); CPA_COMMIT();
    LOAD1(1, 1); CPA_COMMIT();
    LOAD1(2, 2); CPA_COMMIT();
    LOAD1(3, 3); CPA_COMMIT();

    int cs = 0, ls = 4;
    for (int k = 0; k < NK1; k += 2) {
        CPA_WAIT(2);                 // 2 newest groups outstanding -> stages k,k+1 done
        __syncthreads();             // publish stages k,k+1; retire reads <= k-1
        int cs1 = (cs + 1 == NSTG1) ? 0 : cs + 1;

        LDSM_STEP(0, cs, 0);
        if (k + 4 < NK1) LOAD1(k + 4, ls);
        CPA_COMMIT();
        if (++ls == NSTG1) ls = 0;
        LDSM_STEP(1, cs, 1);
        MMA_STEP(0);
        LDSM_STEP(0, cs1, 0);
        MMA_STEP(1);
        if (k + 5 < NK1) LOAD1(k + 5, ls);
        CPA_COMMIT();
        if (++ls == NSTG1) ls = 0;
        LDSM_STEP(1, cs1, 1);
        MMA_STEP(0);
        MMA_STEP(1);

        cs = (cs1 + 1 == NSTG1) ? 0 : cs1 + 1;
    }
#undef LOAD1
#undef LDSM_STEP
#undef MMA_STEP

    // epilogue: h = fp16(silu(g) * u)
#pragma unroll
    for (int mt = 0; mt < 4; mt++) {
#pragma unroll
        for (int nt = 0; nt < 4; nt++) {
            int r0 = m0 + wm0 + mt * 16 + grp;
            int cc = n0 + wn0 + nt * 8 + 2 * tg;
#pragma unroll
            for (int h = 0; h < 2; h++) {
                int row = r0 + h * 8;
                if (row < cnt) {
                    float gv0 = accG[mt][nt][2 * h + 0], uv0 = accU[mt][nt][2 * h + 0];
                    float gv1 = accG[mt][nt][2 * h + 1], uv1 = accU[mt][nt][2 * h + 1];
                    float h0 = (gv0 / (1.f + __expf(-gv0))) * uv0;
                    float h1 = (gv1 / (1.f + __expf(-gv1))) * uv1;
                    *(__half2*)&g_Hh[((size_t)e * CAP + row) * H_DIM + cc] =
                        __floats2half2_rn(h0, h1);
                }
            }
        }
    }
}

// ---------------- GEMM2: Y = wgt * (Hh @ W3[e]^T), fp16 ----------------------
// Unchanged from R11: 256 threads, warp tile 64x32, occ 2, 5-stage ring.
__global__ __launch_bounds__(256, 2)
void k_ffn2() {
    int e  = blockIdx.x >> 5;
    int m0 = (blockIdx.x & 31) * BM;
    int cnt = g_cnt[e];
    if (m0 >= cnt) return;
    int n0 = blockIdx.y * BN;

    extern __shared__ char sm[];

    int tid  = threadIdx.x;
    int wid  = tid >> 5, lane = tid & 31;
    int wm0  = (wid & 1) * 64;
    int wn0  = (wid >> 1) * 32;
    int grp  = lane >> 2, tg = lane & 3;

    int lt = lane >> 3, lr = lane & 7;
    uint32_t smb = s2u(sm);
    uint32_t aAdr = smb + (uint32_t)((wm0 + (lt & 1) * 8 + lr) * RSB + (lt >> 1) * 16);
    uint32_t bAdr = smb + (uint32_t)((wn0 + (lt >> 1) * 8 + lr) * RSB + (lt & 1) * 16);

    int lrow = tid >> 1;
    int lch  = (tid & 1) * 16;
    const __half* aS = g_Hh  + ((size_t)e * CAP + m0 + lrow) * H_DIM + lch;
    const __half* bS = g_W3h + ((size_t)e * D_DIM + n0 + lrow) * H_DIM + lch;
    uint32_t dst = smb + (uint32_t)(lrow * RSB + (tid & 1) * 32);

#define LOAD2(k, stg) do {                                                      \
        int kc = (k) * BK;                                                      \
        uint32_t d0 = dst + (uint32_t)(stg) * STG2_B;                           \
        CPA16(d0,           aS + kc); CPA16(d0 + 16,           aS + kc + 8);    \
        CPA16(d0 + ATILE_B, bS + kc); CPA16(d0 + ATILE_B + 16, bS + kc + 8);    \
    } while (0)

    float acc[4][4][4];
#pragma unroll
    for (int i = 0; i < 4; i++)
#pragma unroll
        for (int j = 0; j < 4; j++)
#pragma unroll
            for (int r = 0; r < 4; r++) acc[i][j][r] = 0.f;

#define COMPUTE2(cs) do {                                                       \
        uint32_t sA = aAdr + (uint32_t)((cs) * STG2_B);                         \
        uint32_t sB = bAdr + (uint32_t)((cs) * STG2_B + ATILE_B);               \
        _Pragma("unroll")                                                       \
        for (int ks = 0; ks < 2; ks++) {                                        \
            uint32_t a[4][4];                                                   \
            _Pragma("unroll")                                                   \
            for (int mt = 0; mt < 4; mt++)                                      \
                LDSM_X4(a[mt], sA + (uint32_t)(mt * 16 * RSB + ks * 32));       \
            uint32_t b[2][4];                                                   \
            _Pragma("unroll")                                                   \
            for (int p = 0; p < 2; p++)                                         \
                LDSM_X4(b[p], sB + (uint32_t)(p * 16 * RSB + ks * 32));         \
            _Pragma("unroll")                                                   \
            for (int mt = 0; mt < 4; mt++)                                      \
                _Pragma("unroll")                                               \
                for (int nt = 0; nt < 4; nt++)                                  \
                    MMA_F16(acc[mt][nt], a[mt], &b[nt >> 1][(nt & 1) * 2]);     \
        }                                                                       \
    } while (0)

    LOAD2(0, 0); CPA_COMMIT();
    LOAD2(1, 1); CPA_COMMIT();
    LOAD2(2, 2); CPA_COMMIT();

    int cs = 0, ls = 3;
    for (int k = 0; k < NK2; k += 2) {
        CPA_WAIT(1);
        __syncthreads();
        if (k + 3 < NK2) LOAD2(k + 3, ls);
        CPA_COMMIT();
        if (++ls == NSTG2) ls = 0;
        COMPUTE2(cs);
        if (++cs == NSTG2) cs = 0;
        if (k + 4 < NK2) LOAD2(k + 4, ls);
        CPA_COMMIT();
        if (++ls == NSTG2) ls = 0;
        COMPUTE2(cs);
        if (++cs == NSTG2) cs = 0;
    }
#undef LOAD2
#undef COMPUTE2

#pragma unroll
    for (int mt = 0; mt < 4; mt++) {
        int r0 = m0 + wm0 + mt * 16 + grp;
#pragma unroll
        for (int h = 0; h < 2; h++) {
            int row = r0 + h * 8;
            if (row < cnt) {
                float w = g_wgt[e * CAP + row];
#pragma unroll
                for (int nt = 0; nt < 4; nt++) {
                    int cc = n0 + wn0 + nt * 8 + 2 * tg;
                    float2 o;
                    o.x = acc[mt][nt][2 * h + 0] * w;
                    o.y = acc[mt][nt][2 * h + 1] * w;
                    *(float2*)&g_Y[((size_t)e * CAP + row) * D_DIM + cc] = o;
                }
            }
        }
    }
}

// -----------------------------------------------------------------------------
extern "C" void kernel_launch(void* const* d_in, const int* in_sizes, int n_in,
                              void* d_out, int out_size) {
    const float* x  = (const float*)d_in[0];
    const float* Wg = (const float*)d_in[1];
    const float* W1 = (const float*)d_in[2];
    const float* W2 = (const float*)d_in[3];
    const float* W3 = (const float*)d_in[4];
    float* out = (float*)d_out;

    cudaFuncSetAttribute(k_ffn1, cudaFuncAttributeMaxDynamicSharedMemorySize, SMEM1_BYTES);
    cudaFuncSetAttribute(k_ffn2, cudaFuncAttributeMaxDynamicSharedMemorySize, SMEM2_BYTES);

    void *p_xc, *p_w1, *p_w2, *p_w3;
    cudaGetSymbolAddress(&p_xc, g_xch);
    cudaGetSymbolAddress(&p_w1, g_W1h);
    cudaGetSymbolAddress(&p_w2, g_W2h);
    cudaGetSymbolAddress(&p_w3, g_W3h);

    long n4_total = N4X + 3 * N4W;                     // 18350080
    int  nblk     = (int)((n4_total + 511) / 512);     // 35840

    k_round_all<<<nblk, 256>>>((const float4*)x,  (const float4*)W1,
                               (const float4*)W2, (const float4*)W3,
                               (__half2*)p_xc, (__half2*)p_w1,
                               (__half2*)p_w2, (__half2*)p_w3);        // 1
    k_zero<<<1, 32>>>();                                               // 2
    k_gate<<<T_TOK / 8, 256>>>(x, Wg);                                 // 3

    dim3 g1(E_NUM * (CAP / BM), H_DIM / BN);   // (256, 22)
    k_ffn1<<<g1, 256, SMEM1_BYTES>>>();                                // 4 <- profile target
    dim3 g2(E_NUM * (CAP / BM), D_DIM / BN);   // (256, 8)
    k_ffn2<<<g2, 256, SMEM2_BYTES>>>();                                // 5 <- profile target

    k_combine<<<(T_TOK * D_DIM / 4) / 256, 256>>>(out);                // 6
}

// round 14
// speedup vs baseline: 2.5610x; 1.0180x over previous
#include <cuda_runtime.h>
#include <cuda_fp16.h>
#include <cstdint>
#include <math.h>

// ---------------- problem constants ------------------------------------------
#define T_TOK 4096
#define D_DIM 1024
#define H_DIM 2816
#define E_NUM 8
#define CAP   4096

#define BM 128
#define BN 128
#define BK 32                      // K halves per stage: 64B data/row
#define RSB 80                     // padded smem row stride in BYTES
#define ATILE_B (BM * RSB)         // 10240 bytes per 128-row tile
#define NK1 (D_DIM / BK)           // 32
#define NK2 (H_DIM / BK)           // 88
#define NSTG1 6                    // ffn1 ring depth (preload 4)
#define NSTG2 5                    // ffn2 ring depth (preload 3, occ 2)

#define STG1_B (3 * ATILE_B)                   // A + B1 + B2 = 30720
#define STG2_B (2 * ATILE_B)                   // A + B = 20480
#define SMEM1_BYTES (NSTG1 * STG1_B)           // 184320
#define SMEM2_BYTES (NSTG2 * STG2_B)           // 102400

#define N4X ((long)T_TOK * D_DIM / 4)          // 1048576
#define N4W ((long)E_NUM * H_DIM * D_DIM / 4)  // 5767168

// ---------------- static device scratch --------------------------------------
__device__ __half g_xch[(size_t)T_TOK * D_DIM];
__device__ __half g_W1h[(size_t)E_NUM * H_DIM * D_DIM];
__device__ __half g_W2h[(size_t)E_NUM * H_DIM * D_DIM];
__device__ __half g_W3h[(size_t)E_NUM * D_DIM * H_DIM];
__device__ __half g_Hh [(size_t)E_NUM * CAP * H_DIM];
__device__ int    g_tok[E_NUM * CAP];
__device__ float  g_wgt[E_NUM * CAP];
__device__ int    g_cnt[E_NUM];

// ---------------- helpers -----------------------------------------------------
__device__ __forceinline__ uint32_t s2u(const void* p) {
    uint32_t a;
    asm("{ .reg .u64 t; cvta.to.shared.u64 t, %1; cvt.u32.u64 %0, t; }" : "=r"(a) : "l"(p));
    return a;
}

#define CPA16(s, g) asm volatile("cp.async.cg.shared.global [%0], [%1], 16;" :: "r"(s), "l"(g))
#define CPA_COMMIT() asm volatile("cp.async.commit_group;" ::: "memory")
#define CPA_WAIT(n)  asm volatile("cp.async.wait_group %0;" :: "n"(n) : "memory")

#define LDSM_X4(r, addr)                                                          \
    asm volatile("ldmatrix.sync.aligned.m8n8.x4.shared.b16 {%0,%1,%2,%3}, [%4];"  \
        : "=r"((r)[0]), "=r"((r)[1]), "=r"((r)[2]), "=r"((r)[3]) : "r"(addr))

#define MMA_F16(d, a, b)                                                          \
    asm volatile(                                                                 \
        "mma.sync.aligned.m16n8k16.row.col.f32.f16.f16.f32 "                      \
        "{%0,%1,%2,%3},{%4,%5,%6,%7},{%8,%9},{%0,%1,%2,%3};"                      \
        : "+f"((d)[0]), "+f"((d)[1]), "+f"((d)[2]), "+f"((d)[3])                  \
        : "r"((a)[0]), "r"((a)[1]), "r"((a)[2]), "r"((a)[3]),                     \
          "r"((b)[0]), "r"((b)[1]))

// ---------------- conversion pass fp32 -> fp16 (x, W1, W2, W3) ---------------
__global__ void k_round_all(const float4* __restrict__ x,
                            const float4* __restrict__ W1,
                            const float4* __restrict__ W2,
                            const float4* __restrict__ W3,
                            __half2* __restrict__ xc,
                            __half2* __restrict__ w1c,
                            __half2* __restrict__ w2c,
                            __half2* __restrict__ w3c) {
    const long total = N4X + 3 * N4W;
    long base = (long)blockIdx.x * 512 + threadIdx.x;
#pragma unroll
    for (int r = 0; r < 2; r++) {
        long i = base + r * 256;
        if (i >= total) return;
        const float4* s;
        __half2* d;
        long off;
        if (i < N4X) { s = x; d = xc; off = i; }
        else {
            long w = i - N4X;
            if (w < N4W)          { s = W1; d = w1c; off = w; }
            else if (w < 2 * N4W) { s = W2; d = w2c; off = w - N4W; }
            else                  { s = W3; d = w3c; off = w - 2 * N4W; }
        }
        float4 v = s[off];
        d[off * 2 + 0] = __floats2half2_rn(v.x, v.y);
        d[off * 2 + 1] = __floats2half2_rn(v.z, v.w);
    }
}

// ---------------- zero pass: out buffer + expert counters --------------------
__global__ void k_zero_all(float4* __restrict__ out) {
    int i = blockIdx.x * 256 + threadIdx.x;
    float4 z; z.x = 0.f; z.y = 0.f; z.z = 0.f; z.w = 0.f;
    out[i] = z;
    if (blockIdx.x == 0 && threadIdx.x < E_NUM) g_cnt[threadIdx.x] = 0;
}

// ---------------- gating: scores + top-2 + scatter ---------------------------
__global__ void k_gate(const float* __restrict__ x, const float* __restrict__ Wg) {
    int t = blockIdx.x * (blockDim.x >> 5) + (threadIdx.x >> 5);
    int lane = threadIdx.x & 31;
    if (t >= T_TOK) return;
    const float4* xr = (const float4*)(x + (size_t)t * D_DIM);
    float acc[E_NUM];
#pragma unroll
    for (int e = 0; e < E_NUM; e++) acc[e] = 0.f;
    for (int i = lane; i < D_DIM / 4; i += 32) {
        float4 xv = xr[i];
#pragma unroll
        for (int e = 0; e < E_NUM; e++) {
            float4 wv = ((const float4*)(Wg + (size_t)e * D_DIM))[i];
            acc[e] += xv.x * wv.x + xv.y * wv.y + xv.z * wv.z + xv.w * wv.w;
        }
    }
#pragma unroll
    for (int e = 0; e < E_NUM; e++)
#pragma unroll
        for (int o = 16; o > 0; o >>= 1)
            acc[e] += __shfl_xor_sync(0xffffffffu, acc[e], o);
    if (lane == 0) {
        int e0 = 0; float v0 = acc[0];
#pragma unroll
        for (int e = 1; e < E_NUM; e++) if (acc[e] > v0) { v0 = acc[e]; e0 = e; }
        int e1 = -1; float v1 = -INFINITY;
#pragma unroll
        for (int e = 0; e < E_NUM; e++)
            if (e != e0 && acc[e] > v1) { v1 = acc[e]; e1 = e; }
        int i0 = atomicAdd(&g_cnt[e0], 1);
        g_tok[e0 * CAP + i0] = t; g_wgt[e0 * CAP + i0] = v0;
        int i1 = atomicAdd(&g_cnt[e1], 1);
        g_tok[e1 * CAP + i1] = t; g_wgt[e1 * CAP + i1] = v1;
    }
}

// ---------------- GEMM1: Hh = silu(X W1^T) * (X W2^T), fp16 ------------------
// Split-role: 512 threads = 8 positions (64x32 subtile) x 2 roles (gate/up).
// Each warp holds ONE accumulator set (64 regs) -> 4 warps/SMSP, no spills.
// 6-stage cp.async ring, preload 4, barrier per 2 stages.
__global__ __launch_bounds__(512, 1)
void k_ffn1() {
    int e  = blockIdx.x >> 5;
    int m0 = (blockIdx.x & 31) * BM;
    int cnt = g_cnt[e];
    if (m0 >= cnt) return;
    int n0 = blockIdx.y * BN;

    extern __shared__ char sm[];

    int tid  = threadIdx.x;
    int wid  = tid >> 5, lane = tid & 31;
    int pos  = wid >> 1;               // 0..7: (pos&1)->m half, (pos>>1)->n quarter
    int role = wid & 1;                // 0 = gate (W1), 1 = up (W2)
    int wm0  = (pos & 1) * 64;
    int wn0  = (pos >> 1) * 32;
    int grp  = lane >> 2, tg = lane & 3;

    int lt = lane >> 3, lr = lane & 7;
    uint32_t smb = s2u(sm);
    uint32_t aAdr = smb + (uint32_t)((wm0 + (lt & 1) * 8 + lr) * RSB + (lt >> 1) * 16);
    uint32_t bAdr = smb + (uint32_t)((wn0 + (lt >> 1) * 8 + lr) * RSB + (lt & 1) * 16)
                  + (uint32_t)((1 + role) * ATILE_B);   // B1 tile or B2 tile

    // loader: 512 threads, 3x CPA16 each (A, B1, B2). row = tid/4, 16B quarter = tid&3
    int lrow = tid >> 2;
    int lq   = tid & 3;
    int tok  = g_tok[e * CAP + m0 + lrow];
    tok = min(max(tok, 0), T_TOK - 1);
    const __half* aS  = g_xch + (size_t)tok * D_DIM + lq * 8;
    const __half* b1S = g_W1h + ((size_t)e * H_DIM + n0 + lrow) * D_DIM + lq * 8;
    const __half* b2S = g_W2h + ((size_t)e * H_DIM + n0 + lrow) * D_DIM + lq * 8;
    uint32_t dst = smb + (uint32_t)(lrow * RSB + lq * 16);

#define LOAD1(k, stg) do {                                                      \
        int kc = (k) * BK;                                                      \
        uint32_t d0 = dst + (uint32_t)(stg) * STG1_B;                           \
        CPA16(d0,               aS  + kc);                                      \
        CPA16(d0 + ATILE_B,     b1S + kc);                                      \
        CPA16(d0 + 2 * ATILE_B, b2S + kc);                                      \
    } while (0)

    float acc[4][4][4];
#pragma unroll
    for (int i = 0; i < 4; i++)
#pragma unroll
        for (int j = 0; j < 4; j++)
#pragma unroll
            for (int r = 0; r < 4; r++) acc[i][j][r] = 0.f;

#define COMPUTE1(cs) do {                                                       \
        uint32_t sA = aAdr + (uint32_t)((cs) * STG1_B);                         \
        uint32_t sB = bAdr + (uint32_t)((cs) * STG1_B);                         \
        _Pragma("unroll")                                                       \
        for (int ks = 0; ks < 2; ks++) {                                        \
            uint32_t a[4][4];                                                   \
            _Pragma("unroll")                                                   \
            for (int mt = 0; mt < 4; mt++)                                      \
                LDSM_X4(a[mt], sA + (uint32_t)(mt * 16 * RSB + ks * 32));       \
            uint32_t b[2][4];                                                   \
            _Pragma("unroll")                                                   \
            for (int p = 0; p < 2; p++)                                         \
                LDSM_X4(b[p], sB + (uint32_t)(p * 16 * RSB + ks * 32));         \
            _Pragma("unroll")                                                   \
            for (int mt = 0; mt < 4; mt++)                                      \
                _Pragma("unroll")                                               \
                for (int nt = 0; nt < 4; nt++)                                  \
                    MMA_F16(acc[mt][nt], a[mt], &b[nt >> 1][(nt & 1) * 2]);     \
        }                                                                       \
    } while (0)

    LOAD1(0, 0); CPA_COMMIT();
    LOAD1(1, 1); CPA_COMMIT();
    LOAD1(2, 2); CPA_COMMIT();
    LOAD1(3, 3); CPA_COMMIT();

    int cs = 0, ls = 4;
    for (int k = 0; k < NK1; k += 2) {
        CPA_WAIT(2);                 // 2 newest groups outstanding -> stages k,k+1 done
        __syncthreads();             // publish stages k,k+1; retire reads <= k-1
        if (k + 4 < NK1) LOAD1(k + 4, ls);
        CPA_COMMIT();
        if (++ls == NSTG1) ls = 0;
        COMPUTE1(cs);
        if (++cs == NSTG1) cs = 0;
        if (k + 5 < NK1) LOAD1(k + 5, ls);
        CPA_COMMIT();
        if (++ls == NSTG1) ls = 0;
        COMPUTE1(cs);
        if (++cs == NSTG1) cs = 0;
    }
#undef LOAD1
#undef COMPUTE1

    // ---------------- epilogue: exchange silu(gate) via smem -----------------
    // position p owns a 64x32 fp32 buffer, padded stride 34 floats (8B-aligned)
    const int XS = 34;
    float* ex = (float*)sm + pos * 64 * XS;

    __syncthreads();                 // ring smem dead; safe to reuse
    if (role == 0) {
#pragma unroll
        for (int mt = 0; mt < 4; mt++)
#pragma unroll
            for (int nt = 0; nt < 4; nt++)
#pragma unroll
                for (int h = 0; h < 2; h++) {
                    int rloc = mt * 16 + h * 8 + grp;
                    int cloc = nt * 8 + 2 * tg;
                    float g0 = acc[mt][nt][2 * h + 0];
                    float g1 = acc[mt][nt][2 * h + 1];
                    float2 s;
                    s.x = g0 / (1.f + __expf(-g0));
                    s.y = g1 / (1.f + __expf(-g1));
                    *(float2*)&ex[rloc * XS + cloc] = s;
                }
    }
    __syncthreads();
    if (role == 1) {
#pragma unroll
        for (int mt = 0; mt < 4; mt++)
#pragma unroll
            for (int nt = 0; nt < 4; nt++)
#pragma unroll
                for (int h = 0; h < 2; h++) {
                    int rloc = mt * 16 + h * 8 + grp;
                    int row  = m0 + wm0 + rloc;
                    if (row < cnt) {
                        int cloc = nt * 8 + 2 * tg;
                        float2 s = *(const float2*)&ex[rloc * XS + cloc];
                        float h0 = s.x * acc[mt][nt][2 * h + 0];
                        float h1 = s.y * acc[mt][nt][2 * h + 1];
                        *(__half2*)&g_Hh[((size_t)e * CAP + row) * H_DIM +
                                         n0 + wn0 + cloc] = __floats2half2_rn(h0, h1);
                    }
                }
    }
}

// ---------------- GEMM2: out[t] += wgt * (Hh @ W3[e]^T), fp16 ----------------
// 256 threads, warp tile 64x32, occ 2, 5-stage ring; atomicAdd epilogue
// (each out element receives exactly 2 commutative fp32 adds -> deterministic).
__global__ __launch_bounds__(256, 2)
void k_ffn2(float* __restrict__ out) {
    int e  = blockIdx.x >> 5;
    int m0 = (blockIdx.x & 31) * BM;
    int cnt = g_cnt[e];
    if (m0 >= cnt) return;
    int n0 = blockIdx.y * BN;

    extern __shared__ char sm[];

    int tid  = threadIdx.x;
    int wid  = tid >> 5, lane = tid & 31;
    int wm0  = (wid & 1) * 64;
    int wn0  = (wid >> 1) * 32;
    int grp  = lane >> 2, tg = lane & 3;

    int lt = lane >> 3, lr = lane & 7;
    uint32_t smb = s2u(sm);
    uint32_t aAdr = smb + (uint32_t)((wm0 + (lt & 1) * 8 + lr) * RSB + (lt >> 1) * 16);
    uint32_t bAdr = smb + (uint32_t)((wn0 + (lt >> 1) * 8 + lr) * RSB + (lt & 1) * 16);

    int lrow = tid >> 1;
    int lch  = (tid & 1) * 16;
    const __half* aS = g_Hh  + ((size_t)e * CAP + m0 + lrow) * H_DIM + lch;
    const __half* bS = g_W3h + ((size_t)e * D_DIM + n0 + lrow) * H_DIM + lch;
    uint32_t dst = smb + (uint32_t)(lrow * RSB + (tid & 1) * 32);

#define LOAD2(k, stg) do {                                                      \
        int kc = (k) * BK;                                                      \
        uint32_t d0 = dst + (uint32_t)(stg) * STG2_B;                           \
        CPA16(d0,           aS + kc); CPA16(d0 + 16,           aS + kc + 8);    \
        CPA16(d0 + ATILE_B, bS + kc); CPA16(d0 + ATILE_B + 16, bS + kc + 8);    \
    } while (0)

    float acc[4][4][4];
#pragma unroll
    for (int i = 0; i < 4; i++)
#pragma unroll
        for (int j = 0; j < 4; j++)
#pragma unroll
            for (int r = 0; r < 4; r++) acc[i][j][r] = 0.f;

#define COMPUTE2(cs) do {                                                       \
        uint32_t sA = aAdr + (uint32_t)((cs) * STG2_B);                         \
        uint32_t sB = bAdr + (uint32_t)((cs) * STG2_B + ATILE_B);               \
        _Pragma("unroll")                                                       \
        for (int ks = 0; ks < 2; ks++) {                                        \
            uint32_t a[4][4];                                                   \
            _Pragma("unroll")                                                   \
            for (int mt = 0; mt < 4; mt++)                                      \
                LDSM_X4(a[mt], sA + (uint32_t)(mt * 16 * RSB + ks * 32));       \
            uint32_t b[2][4];                                                   \
            _Pragma("unroll")                                                   \
            for (int p = 0; p < 2; p++)                                         \
                LDSM_X4(b[p], sB + (uint32_t)(p * 16 * RSB + ks * 32));         \
            _Pragma("unroll")                                                   \
            for (int mt = 0; mt < 4; mt++)                                      \
                _Pragma("unroll")                                               \
                for (int nt = 0; nt < 4; nt++)                                  \
                    MMA_F16(acc[mt][nt], a[mt], &b[nt >> 1][(nt & 1) * 2]);     \
        }                                                                       \
    } while (0)

    LOAD2(0, 0); CPA_COMMIT();
    LOAD2(1, 1); CPA_COMMIT();
    LOAD2(2, 2); CPA_COMMIT();

    int cs = 0, ls = 3;
    for (int k = 0; k < NK2; k += 2) {
        CPA_WAIT(1);
        __syncthreads();
        if (k + 3 < NK2) LOAD2(k + 3, ls);
        CPA_COMMIT();
        if (++ls == NSTG2) ls = 0;
        COMPUTE2(cs);
        if (++cs == NSTG2) cs = 0;
        if (k + 4 < NK2) LOAD2(k + 4, ls);
        CPA_COMMIT();
        if (++ls == NSTG2) ls = 0;
        COMPUTE2(cs);
        if (++cs == NSTG2) cs = 0;
    }
#undef LOAD2
#undef COMPUTE2

#pragma unroll
    for (int mt = 0; mt < 4; mt++) {
        int r0 = m0 + wm0 + mt * 16 + grp;
#pragma unroll
        for (int h = 0; h < 2; h++) {
            int row = r0 + h * 8;
            if (row < cnt) {
                float w = g_wgt[e * CAP + row];
                int t   = g_tok[e * CAP + row];
                float* op = out + (size_t)t * D_DIM;
#pragma unroll
                for (int nt = 0; nt < 4; nt++) {
                    int cc = n0 + wn0 + nt * 8 + 2 * tg;
                    atomicAdd(op + cc,     w * acc[mt][nt][2 * h + 0]);
                    atomicAdd(op + cc + 1, w * acc[mt][nt][2 * h + 1]);
                }
            }
        }
    }
}

// -----------------------------------------------------------------------------
extern "C" void kernel_launch(void* const* d_in, const int* in_sizes, int n_in,
                              void* d_out, int out_size) {
    const float* x  = (const float*)d_in[0];
    const float* Wg = (const float*)d_in[1];
    const float* W1 = (const float*)d_in[2];
    const float* W2 = (const float*)d_in[3];
    const float* W3 = (const float*)d_in[4];
    float* out = (float*)d_out;

    cudaFuncSetAttribute(k_ffn1, cudaFuncAttributeMaxDynamicSharedMemorySize, SMEM1_BYTES);
    cudaFuncSetAttribute(k_ffn2, cudaFuncAttributeMaxDynamicSharedMemorySize, SMEM2_BYTES);

    void *p_xc, *p_w1, *p_w2, *p_w3;
    cudaGetSymbolAddress(&p_xc, g_xch);
    cudaGetSymbolAddress(&p_w1, g_W1h);
    cudaGetSymbolAddress(&p_w2, g_W2h);
    cudaGetSymbolAddress(&p_w3, g_W3h);

    long n4_total = N4X + 3 * N4W;                     // 18350080
    int  nblk     = (int)((n4_total + 511) / 512);     // 35840

    k_round_all<<<nblk, 256>>>((const float4*)x,  (const float4*)W1,
                               (const float4*)W2, (const float4*)W3,
                               (__half2*)p_xc, (__half2*)p_w1,
                               (__half2*)p_w2, (__half2*)p_w3);        // 1
    k_zero_all<<<(T_TOK * D_DIM / 4) / 256, 256>>>((float4*)out);      // 2
    k_gate<<<T_TOK / 8, 256>>>(x, Wg);                                 // 3

    dim3 g1(E_NUM * (CAP / BM), H_DIM / BN);   // (256, 22)
    k_ffn1<<<g1, 512, SMEM1_BYTES>>>();                                // 4 <- profile target
    dim3 g2(E_NUM * (CAP / BM), D_DIM / BN);   // (256, 8)
    k_ffn2<<<g2, 256, SMEM2_BYTES>>>(out);                             // 5
}

// round 15
// speedup vs baseline: 2.6663x; 1.0411x over previous
#include <cuda_runtime.h>
#include <cuda_fp16.h>
#include <cstdint>
#include <math.h>

// ---------------- problem constants ------------------------------------------
#define T_TOK 4096
#define D_DIM 1024
#define H_DIM 2816
#define E_NUM 8
#define CAP   4096

#define BM 128
#define BN 128
#define BK 32                      // K halves per stage: 64B data/row
#define RSB 80                     // padded smem row stride in BYTES
#define ATILE_B (BM * RSB)         // 10240 bytes per 128-row tile
#define NK1 (D_DIM / BK)           // 32
#define NK2 (H_DIM / BK)           // 88
#define NSTG1 6                    // ffn1 ring depth (preload 4)
#define NSTG2 5                    // ffn2 ring depth (preload 3, occ 2)
#define NB1  (H_DIM / BN)          // 22 n-blocks in ffn1; blockIdx.y==NB1 -> W3 conv

#define STG1_B (3 * ATILE_B)                   // A + B1 + B2 = 30720
#define STG2_B (2 * ATILE_B)                   // A + B = 20480
#define SMEM1_BYTES (NSTG1 * STG1_B)           // 184320
#define SMEM2_BYTES (NSTG2 * STG2_B)           // 102400

#define N4W ((long)E_NUM * H_DIM * D_DIM / 4)  // 5767168 float4 per weight tensor

#define GATE_BLKS 512                          // 8 tokens per 256-thread block
#define CONV12_BLKS 1024                       // W1+W2 converter blocks in K1
#define CONV3_BLKS 256                         // W3 converter blocks in K2 (y==NB1)

// ---------------- static device scratch --------------------------------------
__device__ __half g_xch[(size_t)T_TOK * D_DIM];
__device__ __half g_W1h[(size_t)E_NUM * H_DIM * D_DIM];
__device__ __half g_W2h[(size_t)E_NUM * H_DIM * D_DIM];
__device__ __half g_W3h[(size_t)E_NUM * D_DIM * H_DIM];
__device__ __half g_Hh [(size_t)E_NUM * CAP * H_DIM];
__device__ int    g_tok[E_NUM * CAP];
__device__ float  g_wgt[E_NUM * CAP];
__device__ int    g_cnt[E_NUM];

// ---------------- helpers -----------------------------------------------------
__device__ __forceinline__ uint32_t s2u(const void* p) {
    uint32_t a;
    asm("{ .reg .u64 t; cvta.to.shared.u64 t, %1; cvt.u32.u64 %0, t; }" : "=r"(a) : "l"(p));
    return a;
}

#define CPA16(s, g) asm volatile("cp.async.cg.shared.global [%0], [%1], 16;" :: "r"(s), "l"(g))
#define CPA_COMMIT() asm volatile("cp.async.commit_group;" ::: "memory")
#define CPA_WAIT(n)  asm volatile("cp.async.wait_group %0;" :: "n"(n) : "memory")

#define LDSM_X4(r, addr)                                                          \
    asm volatile("ldmatrix.sync.aligned.m8n8.x4.shared.b16 {%0,%1,%2,%3}, [%4];"  \
        : "=r"((r)[0]), "=r"((r)[1]), "=r"((r)[2]), "=r"((r)[3]) : "r"(addr))

#define MMA_F16(d, a, b)                                                          \
    asm volatile(                                                                 \
        "mma.sync.aligned.m16n8k16.row.col.f32.f16.f16.f32 "                      \
        "{%0,%1,%2,%3},{%4,%5,%6,%7},{%8,%9},{%0,%1,%2,%3};"                      \
        : "+f"((d)[0]), "+f"((d)[1]), "+f"((d)[2]), "+f"((d)[3])                  \
        : "r"((a)[0]), "r"((a)[1]), "r"((a)[2]), "r"((a)[3]),                     \
          "r"((b)[0]), "r"((b)[1]))

__device__ __forceinline__ void conv_f4(const float4* __restrict__ s,
                                        __half2* __restrict__ d, long i) {
    float4 v = s[i];
    d[i * 2 + 0] = __floats2half2_rn(v.x, v.y);
    d[i * 2 + 1] = __floats2half2_rn(v.z, v.w);
}

// ---------------- K1: gating (+x fp16 conversion) + W1/W2 conversion ---------
__global__ void k_front(const float* __restrict__ x,
                        const float* __restrict__ Wg,
                        const float4* __restrict__ W1,
                        const float4* __restrict__ W2,
                        __half2* __restrict__ w1c,
                        __half2* __restrict__ w2c) {
    if (blockIdx.x < GATE_BLKS) {
        // ---- gate: one warp per token; also writes fp16 x row ----
        int t = blockIdx.x * 8 + (threadIdx.x >> 5);
        int lane = threadIdx.x & 31;
        const float4* xr = (const float4*)(x + (size_t)t * D_DIM);
        float acc[E_NUM];
#pragma unroll
        for (int e = 0; e < E_NUM; e++) acc[e] = 0.f;
        for (int i = lane; i < D_DIM / 4; i += 32) {
            float4 xv = xr[i];
            // free fp16 conversion of x while it's in registers
            uint2 u;
            __half2 h0 = __floats2half2_rn(xv.x, xv.y);
            __half2 h1 = __floats2half2_rn(xv.z, xv.w);
            u.x = *(uint32_t*)&h0; u.y = *(uint32_t*)&h1;
            *(uint2*)&g_xch[(size_t)t * D_DIM + i * 4] = u;
#pragma unroll
            for (int e = 0; e < E_NUM; e++) {
                float4 wv = ((const float4*)(Wg + (size_t)e * D_DIM))[i];
                acc[e] += xv.x * wv.x + xv.y * wv.y + xv.z * wv.z + xv.w * wv.w;
            }
        }
#pragma unroll
        for (int e = 0; e < E_NUM; e++)
#pragma unroll
            for (int o = 16; o > 0; o >>= 1)
                acc[e] += __shfl_xor_sync(0xffffffffu, acc[e], o);
        if (lane == 0) {
            int e0 = 0; float v0 = acc[0];
#pragma unroll
            for (int e = 1; e < E_NUM; e++) if (acc[e] > v0) { v0 = acc[e]; e0 = e; }
            int e1 = -1; float v1 = -INFINITY;
#pragma unroll
            for (int e = 0; e < E_NUM; e++)
                if (e != e0 && acc[e] > v1) { v1 = acc[e]; e1 = e; }
            int i0 = atomicAdd(&g_cnt[e0], 1);
            g_tok[e0 * CAP + i0] = t; g_wgt[e0 * CAP + i0] = v0;
            int i1 = atomicAdd(&g_cnt[e1], 1);
            g_tok[e1 * CAP + i1] = t; g_wgt[e1 * CAP + i1] = v1;
        }
    } else {
        // ---- W1 + W2 fp32->fp16 conversion, grid-stride ----
        const long total = 2 * N4W;
        const long stride = (long)CONV12_BLKS * 256;
        for (long i = (long)(blockIdx.x - GATE_BLKS) * 256 + threadIdx.x;
             i < total; i += stride) {
            if (i < N4W) conv_f4(W1, w1c, i);
            else         conv_f4(W2, w2c, i - N4W);
        }
    }
}

// ---------------- K2: GEMM1 (+W3 conversion blocks at y==NB1) ----------------
// Split-role: 512 threads = 8 positions (64x32 subtile) x 2 roles (gate/up).
// 6-stage cp.async ring, preload 4, barrier per 2 stages.
__global__ __launch_bounds__(512, 1)
void k_ffn1(const float4* __restrict__ W3, __half2* __restrict__ w3c) {
    if (blockIdx.y == NB1) {
        // W3 converter blocks (enumerated last -> run in ffn1's tail)
        const long stride = (long)CONV3_BLKS * 512;
        for (long i = (long)blockIdx.x * 512 + threadIdx.x; i < N4W; i += stride)
            conv_f4(W3, w3c, i);
        return;
    }
    int e  = blockIdx.x >> 5;
    int m0 = (blockIdx.x & 31) * BM;
    int cnt = g_cnt[e];
    if (m0 >= cnt) return;
    int n0 = blockIdx.y * BN;

    extern __shared__ char sm[];

    int tid  = threadIdx.x;
    int wid  = tid >> 5, lane = tid & 31;
    int pos  = wid >> 1;
    int role = wid & 1;                // 0 = gate (W1), 1 = up (W2)
    int wm0  = (pos & 1) * 64;
    int wn0  = (pos >> 1) * 32;
    int grp  = lane >> 2, tg = lane & 3;

    int lt = lane >> 3, lr = lane & 7;
    uint32_t smb = s2u(sm);
    uint32_t aAdr = smb + (uint32_t)((wm0 + (lt & 1) * 8 + lr) * RSB + (lt >> 1) * 16);
    uint32_t bAdr = smb + (uint32_t)((wn0 + (lt >> 1) * 8 + lr) * RSB + (lt & 1) * 16)
                  + (uint32_t)((1 + role) * ATILE_B);

    int lrow = tid >> 2;
    int lq   = tid & 3;
    int tok  = g_tok[e * CAP + m0 + lrow];
    tok = min(max(tok, 0), T_TOK - 1);
    const __half* aS  = g_xch + (size_t)tok * D_DIM + lq * 8;
    const __half* b1S = g_W1h + ((size_t)e * H_DIM + n0 + lrow) * D_DIM + lq * 8;
    const __half* b2S = g_W2h + ((size_t)e * H_DIM + n0 + lrow) * D_DIM + lq * 8;
    uint32_t dst = smb + (uint32_t)(lrow * RSB + lq * 16);

#define LOAD1(k, stg) do {                                                      \
        int kc = (k) * BK;                                                      \
        uint32_t d0 = dst + (uint32_t)(stg) * STG1_B;                           \
        CPA16(d0,               aS  + kc);                                      \
        CPA16(d0 + ATILE_B,     b1S + kc);                                      \
        CPA16(d0 + 2 * ATILE_B, b2S + kc);                                      \
    } while (0)

    float acc[4][4][4];
#pragma unroll
    for (int i = 0; i < 4; i++)
#pragma unroll
        for (int j = 0; j < 4; j++)
#pragma unroll
            for (int r = 0; r < 4; r++) acc[i][j][r] = 0.f;

#define COMPUTE1(cs) do {                                                       \
        uint32_t sA = aAdr + (uint32_t)((cs) * STG1_B);                         \
        uint32_t sB = bAdr + (uint32_t)((cs) * STG1_B);                         \
        _Pragma("unroll")                                                       \
        for (int ks = 0; ks < 2; ks++) {                                        \
            uint32_t a[4][4];                                                   \
            _Pragma("unroll")                                                   \
            for (int mt = 0; mt < 4; mt++)                                      \
                LDSM_X4(a[mt], sA + (uint32_t)(mt * 16 * RSB + ks * 32));       \
            uint32_t b[2][4];                                                   \
            _Pragma("unroll")                                                   \
            for (int p = 0; p < 2; p++)                                         \
                LDSM_X4(b[p], sB + (uint32_t)(p * 16 * RSB + ks * 32));         \
            _Pragma("unroll")                                                   \
            for (int mt = 0; mt < 4; mt++)                                      \
                _Pragma("unroll")                                               \
                for (int nt = 0; nt < 4; nt++)                                  \
                    MMA_F16(acc[mt][nt], a[mt], &b[nt >> 1][(nt & 1) * 2]);     \
        }                                                                       \
    } while (0)

    LOAD1(0, 0); CPA_COMMIT();
    LOAD1(1, 1); CPA_COMMIT();
    LOAD1(2, 2); CPA_COMMIT();
    LOAD1(3, 3); CPA_COMMIT();

    int cs = 0, ls = 4;
    for (int k = 0; k < NK1; k += 2) {
        CPA_WAIT(2);
        __syncthreads();
        if (k + 4 < NK1) LOAD1(k + 4, ls);
        CPA_COMMIT();
        if (++ls == NSTG1) ls = 0;
        COMPUTE1(cs);
        if (++cs == NSTG1) cs = 0;
        if (k + 5 < NK1) LOAD1(k + 5, ls);
        CPA_COMMIT();
        if (++ls == NSTG1) ls = 0;
        COMPUTE1(cs);
        if (++cs == NSTG1) cs = 0;
    }
#undef LOAD1
#undef COMPUTE1

    // epilogue: exchange silu(gate) via smem, write fp16 Hh
    const int XS = 34;
    float* ex = (float*)sm + pos * 64 * XS;

    __syncthreads();
    if (role == 0) {
#pragma unroll
        for (int mt = 0; mt < 4; mt++)
#pragma unroll
            for (int nt = 0; nt < 4; nt++)
#pragma unroll
                for (int h = 0; h < 2; h++) {
                    int rloc = mt * 16 + h * 8 + grp;
                    int cloc = nt * 8 + 2 * tg;
                    float g0 = acc[mt][nt][2 * h + 0];
                    float g1 = acc[mt][nt][2 * h + 1];
                    float2 s;
                    s.x = g0 / (1.f + __expf(-g0));
                    s.y = g1 / (1.f + __expf(-g1));
                    *(float2*)&ex[rloc * XS + cloc] = s;
                }
    }
    __syncthreads();
    if (role == 1) {
#pragma unroll
        for (int mt = 0; mt < 4; mt++)
#pragma unroll
            for (int nt = 0; nt < 4; nt++)
#pragma unroll
                for (int h = 0; h < 2; h++) {
                    int rloc = mt * 16 + h * 8 + grp;
                    int row  = m0 + wm0 + rloc;
                    if (row < cnt) {
                        int cloc = nt * 8 + 2 * tg;
                        float2 s = *(const float2*)&ex[rloc * XS + cloc];
                        float h0 = s.x * acc[mt][nt][2 * h + 0];
                        float h1 = s.y * acc[mt][nt][2 * h + 1];
                        *(__half2*)&g_Hh[((size_t)e * CAP + row) * H_DIM +
                                         n0 + wn0 + cloc] = __floats2half2_rn(h0, h1);
                    }
                }
    }
}

// ---------------- K3: GEMM2, out[t] += wgt * (Hh @ W3[e]^T) ------------------
// 256 threads, warp tile 64x32, occ 2, 5-stage ring; atomicAdd epilogue
// (each out element receives exactly 2 commutative fp32 adds -> deterministic).
__global__ __launch_bounds__(256, 2)
void k_ffn2(float* __restrict__ out) {
    int e  = blockIdx.x >> 5;
    int m0 = (blockIdx.x & 31) * BM;
    int cnt = g_cnt[e];
    if (m0 >= cnt) return;
    int n0 = blockIdx.y * BN;

    extern __shared__ char sm[];

    int tid  = threadIdx.x;
    int wid  = tid >> 5, lane = tid & 31;
    int wm0  = (wid & 1) * 64;
    int wn0  = (wid >> 1) * 32;
    int grp  = lane >> 2, tg = lane & 3;

    int lt = lane >> 3, lr = lane & 7;
    uint32_t smb = s2u(sm);
    uint32_t aAdr = smb + (uint32_t)((wm0 + (lt & 1) * 8 + lr) * RSB + (lt >> 1) * 16);
    uint32_t bAdr = smb + (uint32_t)((wn0 + (lt >> 1) * 8 + lr) * RSB + (lt & 1) * 16);

    int lrow = tid >> 1;
    int lch  = (tid & 1) * 16;
    const __half* aS = g_Hh  + ((size_t)e * CAP + m0 + lrow) * H_DIM + lch;
    const __half* bS = g_W3h + ((size_t)e * D_DIM + n0 + lrow) * H_DIM + lch;
    uint32_t dst = smb + (uint32_t)(lrow * RSB + (tid & 1) * 32);

#define LOAD2(k, stg) do {                                                      \
        int kc = (k) * BK;                                                      \
        uint32_t d0 = dst + (uint32_t)(stg) * STG2_B;                           \
        CPA16(d0,           aS + kc); CPA16(d0 + 16,           aS + kc + 8);    \
        CPA16(d0 + ATILE_B, bS + kc); CPA16(d0 + ATILE_B + 16, bS + kc + 8);    \
    } while (0)

    float acc[4][4][4];
#pragma unroll
    for (int i = 0; i < 4; i++)
#pragma unroll
        for (int j = 0; j < 4; j++)
#pragma unroll
            for (int r = 0; r < 4; r++) acc[i][j][r] = 0.f;

#define COMPUTE2(cs) do {                                                       \
        uint32_t sA = aAdr + (uint32_t)((cs) * STG2_B);                         \
        uint32_t sB = bAdr + (uint32_t)((cs) * STG2_B + ATILE_B);               \
        _Pragma("unroll")                                                       \
        for (int ks = 0; ks < 2; ks++) {                                        \
            uint32_t a[4][4];                                                   \
            _Pragma("unroll")                                                   \
            for (int mt = 0; mt < 4; mt++)                                      \
                LDSM_X4(a[mt], sA + (uint32_t)(mt * 16 * RSB + ks * 32));       \
            uint32_t b[2][4];                                                   \
            _Pragma("unroll")                                                   \
            for (int p = 0; p < 2; p++)                                         \
                LDSM_X4(b[p], sB + (uint32_t)(p * 16 * RSB + ks * 32));         \
            _Pragma("unroll")                                                   \
            for (int mt = 0; mt < 4; mt++)                                      \
                _Pragma("unroll")                                               \
                for (int nt = 0; nt < 4; nt++)                                  \
                    MMA_F16(acc[mt][nt], a[mt], &b[nt >> 1][(nt & 1) * 2]);     \
        }                                                                       \
    } while (0)

    LOAD2(0, 0); CPA_COMMIT();
    LOAD2(1, 1); CPA_COMMIT();
    LOAD2(2, 2); CPA_COMMIT();

    int cs = 0, ls = 3;
    for (int k = 0; k < NK2; k += 2) {
        CPA_WAIT(1);
        __syncthreads();
        if (k + 3 < NK2) LOAD2(k + 3, ls);
        CPA_COMMIT();
        if (++ls == NSTG2) ls = 0;
        COMPUTE2(cs);
        if (++cs == NSTG2) cs = 0;
        if (k + 4 < NK2) LOAD2(k + 4, ls);
        CPA_COMMIT();
        if (++ls == NSTG2) ls = 0;
        COMPUTE2(cs);
        if (++cs == NSTG2) cs = 0;
    }
#undef LOAD2
#undef COMPUTE2

#pragma unroll
    for (int mt = 0; mt < 4; mt++) {
        int r0 = m0 + wm0 + mt * 16 + grp;
#pragma unroll
        for (int h = 0; h < 2; h++) {
            int row = r0 + h * 8;
            if (row < cnt) {
                float w = g_wgt[e * CAP + row];
                int t   = g_tok[e * CAP + row];
                float* op = out + (size_t)t * D_DIM;
#pragma unroll
                for (int nt = 0; nt < 4; nt++) {
                    int cc = n0 + wn0 + nt * 8 + 2 * tg;
                    atomicAdd(op + cc,     w * acc[mt][nt][2 * h + 0]);
                    atomicAdd(op + cc + 1, w * acc[mt][nt][2 * h + 1]);
                }
            }
        }
    }
}

// -----------------------------------------------------------------------------
extern "C" void kernel_launch(void* const* d_in, const int* in_sizes, int n_in,
                              void* d_out, int out_size) {
    const float* x  = (const float*)d_in[0];
    const float* Wg = (const float*)d_in[1];
    const float* W1 = (const float*)d_in[2];
    const float* W2 = (const float*)d_in[3];
    const float* W3 = (const float*)d_in[4];
    float* out = (float*)d_out;

    cudaFuncSetAttribute(k_ffn1, cudaFuncAttributeMaxDynamicSharedMemorySize, SMEM1_BYTES);
    cudaFuncSetAttribute(k_ffn2, cudaFuncAttributeMaxDynamicSharedMemorySize, SMEM2_BYTES);

    void *p_xc, *p_w1, *p_w2, *p_w3, *p_cnt;
    cudaGetSymbolAddress(&p_xc, g_xch);
    cudaGetSymbolAddress(&p_w1, g_W1h);
    cudaGetSymbolAddress(&p_w2, g_W2h);
    cudaGetSymbolAddress(&p_w3, g_W3h);
    cudaGetSymbolAddress(&p_cnt, g_cnt);

    // zero: counters + output accumulator (memset nodes, graph-capturable)
    cudaMemsetAsync(p_cnt, 0, E_NUM * sizeof(int));
    cudaMemsetAsync(out, 0, (size_t)T_TOK * D_DIM * sizeof(float));

    // K1: gate (+x conversion) and W1/W2 conversion fused
    k_front<<<GATE_BLKS + CONV12_BLKS, 256>>>(
        x, Wg, (const float4*)W1, (const float4*)W2,
        (__half2*)p_w1, (__half2*)p_w2);

    // K2: ffn1 + W3 converter blocks (y == NB1, enumerated last)
    dim3 g1(E_NUM * (CAP / BM), NB1 + 1);      // (256, 23)
    k_ffn1<<<g1, 512, SMEM1_BYTES>>>((const float4*)W3, (__half2*)p_w3);

    // K3: ffn2 with fused routed accumulation into out
    dim3 g2(E_NUM * (CAP / BM), D_DIM / BN);   // (256, 8)
    k_ffn2<<<g2, 256, SMEM2_BYTES>>>(out);
}